// round 6
// baseline (speedup 1.0000x reference)
#include <cuda_runtime.h>
#include <cuda_bf16.h>
#include <cstdint>

// ---------------------------------------------------------------------------
// Problem constants
// ---------------------------------------------------------------------------
#define BB   4
#define TTT  4096
#define CC   1024
#define HH   16
#define HS   64
#define TCH  128
#define NCH  (TTT / TCH)
#define MM   (BB * TTT)      // 16384 rows
#define KD2  2048            // [hi(1024) | lo(1024)] concat width

// ---------------------------------------------------------------------------
// Device scratch (no cudaMalloc allowed)
// ---------------------------------------------------------------------------
__device__ __nv_bfloat16 g_xr[(size_t)MM * KD2];
__device__ __nv_bfloat16 g_xk[(size_t)MM * KD2];
__device__ __nv_bfloat16 g_xv[(size_t)MM * KD2];
__device__ __nv_bfloat16 g_xg[(size_t)MM * KD2];
__device__ __nv_bfloat16 g_ygb[(size_t)MM * KD2];
__device__ __nv_bfloat16 g_Wr[(size_t)CC * KD2];
__device__ __nv_bfloat16 g_Wk[(size_t)CC * KD2];
__device__ __nv_bfloat16 g_Wv[(size_t)CC * KD2];
__device__ __nv_bfloat16 g_Wg[(size_t)CC * KD2];
__device__ __nv_bfloat16 g_Wo[(size_t)CC * KD2];
__device__ float g_r [(size_t)MM * CC];
__device__ float g_k [(size_t)MM * CC];
__device__ float g_v [(size_t)MM * CC];
__device__ float g_g [(size_t)MM * CC];
__device__ float g_xo[(size_t)MM * CC];
__device__ float g_state[(size_t)BB * HH * NCH * HS * HS];  // 33.5 MB

// ---------------------------------------------------------------------------
// Helpers
// ---------------------------------------------------------------------------
__device__ __forceinline__ uint32_t smem_u32(const void* p) {
    uint32_t a;
    asm("{ .reg .u64 t; cvta.to.shared.u64 t, %1; cvt.u32.u64 %0, t; }"
        : "=r"(a) : "l"(p));
    return a;
}

__device__ __forceinline__ void cp_async16(uint32_t dst, const void* src) {
    asm volatile("cp.async.cg.shared.global [%0], [%1], 16;" :: "r"(dst), "l"(src));
}
#define CP_COMMIT() asm volatile("cp.async.commit_group;" ::: "memory")
#define CP_WAIT2()  asm volatile("cp.async.wait_group 2;" ::: "memory")

__device__ __forceinline__ void ldm_x4(uint32_t& r0, uint32_t& r1,
                                       uint32_t& r2, uint32_t& r3, uint32_t addr) {
    asm volatile("ldmatrix.sync.aligned.m8n8.x4.shared.b16 {%0,%1,%2,%3}, [%4];"
                 : "=r"(r0), "=r"(r1), "=r"(r2), "=r"(r3) : "r"(addr));
}

__device__ __forceinline__ void mma_bf16(float& c0, float& c1, float& c2, float& c3,
                                         uint32_t a0, uint32_t a1, uint32_t a2, uint32_t a3,
                                         uint32_t b0, uint32_t b1) {
    asm volatile("mma.sync.aligned.m16n8k16.row.col.f32.bf16.bf16.f32 "
                 "{%0,%1,%2,%3}, {%4,%5,%6,%7}, {%8,%9}, {%0,%1,%2,%3};"
                 : "+f"(c0), "+f"(c1), "+f"(c2), "+f"(c3)
                 : "r"(a0), "r"(a1), "r"(a2), "r"(a3), "r"(b0), "r"(b1));
}

// smem tile: rows x 32 bf16 (64B/row), 16B chunks XOR-swizzled
__device__ __forceinline__ uint32_t swz(int row, int chunk) {
    return (uint32_t)(row * 64 + ((chunk ^ ((row >> 1) & 3)) << 4));
}

__device__ __forceinline__ void split_bf16(float v, __nv_bfloat16& h, __nv_bfloat16& l) {
    h = __float2bfloat16(v);
    l = __float2bfloat16(v - __bfloat162float(h));
}

// ---------------------------------------------------------------------------
// 0) Weight conversion (all 5 weights in one launch):
//    W (CC x CC fp32) -> [hi | lo] (CC x KD2 bf16)
// ---------------------------------------------------------------------------
__global__ __launch_bounds__(256) void convw_kernel(
    const float* __restrict__ W0, const float* __restrict__ W1,
    const float* __restrict__ W2, const float* __restrict__ W3,
    const float* __restrict__ W4,
    __nv_bfloat16* __restrict__ o0, __nv_bfloat16* __restrict__ o1,
    __nv_bfloat16* __restrict__ o2, __nv_bfloat16* __restrict__ o3,
    __nv_bfloat16* __restrict__ o4)
{
    const float* W;
    __nv_bfloat16* o;
    switch (blockIdx.y) {
        case 0: W = W0; o = o0; break;
        case 1: W = W1; o = o1; break;
        case 2: W = W2; o = o2; break;
        case 3: W = W3; o = o3; break;
        default: W = W4; o = o4; break;
    }
    int idx = blockIdx.x * 256 + threadIdx.x;
    if (idx >= CC * CC) return;
    int r = idx >> 10, c = idx & 1023;
    __nv_bfloat16 h, l;
    split_bf16(W[idx], h, l);
    o[(size_t)r * KD2 + c] = h;
    o[(size_t)r * KD2 + 1024 + c] = l;
}

// ---------------------------------------------------------------------------
// 1) time-shift + 4-way mix -> bf16 hi/lo outputs
// ---------------------------------------------------------------------------
__global__ __launch_bounds__(256) void mix_kernel(
    const float* __restrict__ x,
    const float* __restrict__ tmk, const float* __restrict__ tmv,
    const float* __restrict__ tmr, const float* __restrict__ tmg,
    __nv_bfloat16* __restrict__ xr, __nv_bfloat16* __restrict__ xk,
    __nv_bfloat16* __restrict__ xv, __nv_bfloat16* __restrict__ xg)
{
    int idx = blockIdx.x * blockDim.x + threadIdx.x;   // float4 index
    const int C4 = CC / 4;
    if (idx >= MM * C4) return;
    int c4 = idx % C4;
    int row = idx / C4;
    int t = row % TTT;

    float4 xc = ((const float4*)x)[idx];
    float4 xp = (t > 0) ? ((const float4*)x)[idx - C4] : make_float4(0.f, 0.f, 0.f, 0.f);

    float4 mk = ((const float4*)tmk)[c4];
    float4 mv = ((const float4*)tmv)[c4];
    float4 mr = ((const float4*)tmr)[c4];
    float4 mg = ((const float4*)tmg)[c4];

    size_t base = (size_t)row * KD2 + c4 * 4;

#define MIXV(out, m)                                                          \
    {                                                                         \
        float o0 = xp.x + m.x * (xc.x - xp.x);                                \
        float o1 = xp.y + m.y * (xc.y - xp.y);                                \
        float o2 = xp.z + m.z * (xc.z - xp.z);                                \
        float o3 = xp.w + m.w * (xc.w - xp.w);                                \
        union { __nv_bfloat16 b[4]; uint2 u; } hi, lo;                        \
        split_bf16(o0, hi.b[0], lo.b[0]);                                     \
        split_bf16(o1, hi.b[1], lo.b[1]);                                     \
        split_bf16(o2, hi.b[2], lo.b[2]);                                     \
        split_bf16(o3, hi.b[3], lo.b[3]);                                     \
        *(uint2*)(out + base) = hi.u;                                         \
        *(uint2*)(out + base + 1024) = lo.u;                                  \
    }
    MIXV(xr, mr); MIXV(xk, mk); MIXV(xv, mv); MIXV(xg, mg);
#undef MIXV
}

// ---------------------------------------------------------------------------
// 2) bf16 mma.sync GEMM: C[m,n] = sum_k A[m,k]*W[n,k]  (bf16x3 split, f32 acc)
//    CTA 128x256, BK=32, 8 warps as 2M x 4N, warp tile 64x64.
//    96 stages = 3 passes (hi*hi, hi*lo, lo*hi) x 32 k-blocks.
//    4-stage cp.async pipeline, ONE __syncthreads per stage.
// ---------------------------------------------------------------------------
#define GSTAGES       4
#define GSTAGE_BYTES  24576                     // A 8KB + B 16KB
#define GEMM_SMEM     (GSTAGES * GSTAGE_BYTES)  // 96 KB

__global__ __launch_bounds__(256, 1) void gemm_mma(
    const __nv_bfloat16* __restrict__ A, const __nv_bfloat16* __restrict__ W,
    float* __restrict__ C, int epi)
{
    extern __shared__ __align__(128) char gsm[];

    const int tid = threadIdx.x;
    const int wid = tid >> 5, lane = tid & 31;
    const int wm = wid & 1;          // 0..1 -> M (64 rows each)
    const int wn = wid >> 1;         // 0..3 -> N (64 cols each)
    const int m0 = blockIdx.y * 128;
    const int n0 = blockIdx.x * 256;

    const uint32_t sa0 = smem_u32(gsm);

    float acc[4][8][4];
#pragma unroll
    for (int mt = 0; mt < 4; mt++)
#pragma unroll
        for (int nt = 0; nt < 8; nt++)
#pragma unroll
            for (int q = 0; q < 4; q++) acc[mt][nt][q] = 0.f;

    // loader: A 512 chunks (2/thread), B 1024 chunks (4/thread)
    const int lrowA = tid >> 1;                 // 0..127
    const int lcA0 = (tid & 1) * 2;             // chunks {0,1} or {2,3}

    auto load_stage = [&](int s, int buf) {
        int p = s >> 5, kb = s & 31;
        int aoff = (p == 2) ? 1024 : 0;
        int boff = (p == 1) ? 1024 : 0;
        uint32_t ab = sa0 + buf * GSTAGE_BYTES;
        uint32_t bb = ab + 8192;
        const __nv_bfloat16* Ar = A + (size_t)(m0 + lrowA) * KD2 + aoff + kb * 32;
        const __nv_bfloat16* Br = W + (size_t)(n0 + tid) * KD2 + boff + kb * 32;
#pragma unroll
        for (int c = 0; c < 2; c++)
            cp_async16(ab + swz(lrowA, lcA0 + c), Ar + (lcA0 + c) * 8);
#pragma unroll
        for (int c = 0; c < 4; c++)
            cp_async16(bb + swz(tid, c), Br + c * 8);
    };

    const int NST = 96;
    load_stage(0, 0); CP_COMMIT();
    load_stage(1, 1); CP_COMMIT();
    load_stage(2, 2); CP_COMMIT();

    for (int s = 0; s < NST; s++) {
        CP_WAIT2();                      // stage s resident
        __syncthreads();

        if (s + 3 < NST) load_stage(s + 3, (s + 3) & 3);
        CP_COMMIT();                     // unconditional: uniform group count

        uint32_t ab = sa0 + (s & 3) * GSTAGE_BYTES;
        uint32_t bb = ab + 8192;
#pragma unroll
        for (int kk = 0; kk < 2; kk++) {
            uint32_t a[4][4];
#pragma unroll
            for (int mt = 0; mt < 4; mt++) {
                int row = wm * 64 + mt * 16 + (lane & 15);
                int ch = kk * 2 + (lane >> 4);
                ldm_x4(a[mt][0], a[mt][1], a[mt][2], a[mt][3], ab + swz(row, ch));
            }
            uint32_t b[8][2];
#pragma unroll
            for (int nq = 0; nq < 4; nq++) {
                int row = wn * 64 + nq * 16 + ((lane >> 4) & 1) * 8 + (lane & 7);
                int ch = kk * 2 + ((lane >> 3) & 1);
                ldm_x4(b[nq * 2][0], b[nq * 2][1], b[nq * 2 + 1][0], b[nq * 2 + 1][1],
                       bb + swz(row, ch));
            }
#pragma unroll
            for (int mt = 0; mt < 4; mt++)
#pragma unroll
                for (int nt = 0; nt < 8; nt++)
                    mma_bf16(acc[mt][nt][0], acc[mt][nt][1], acc[mt][nt][2], acc[mt][nt][3],
                             a[mt][0], a[mt][1], a[mt][2], a[mt][3],
                             b[nt][0], b[nt][1]);
        }
    }

    // epilogue: direct float2 stores
#pragma unroll
    for (int mt = 0; mt < 4; mt++) {
        int gr = m0 + wm * 64 + mt * 16 + (lane >> 2);
#pragma unroll
        for (int nt = 0; nt < 8; nt++) {
            int gc = n0 + wn * 64 + nt * 8 + (lane & 3) * 2;
            float v0 = acc[mt][nt][0], v1 = acc[mt][nt][1];
            float v2 = acc[mt][nt][2], v3 = acc[mt][nt][3];
            if (epi) {
                v0 = v0 / (1.f + expf(-v0));
                v1 = v1 / (1.f + expf(-v1));
                v2 = v2 / (1.f + expf(-v2));
                v3 = v3 / (1.f + expf(-v3));
            }
            *(float2*)&C[(size_t)gr * CC + gc]       = make_float2(v0, v1);
            *(float2*)&C[(size_t)(gr + 8) * CC + gc] = make_float2(v2, v3);
        }
    }
}

// ---------------------------------------------------------------------------
// 3a) WKV phase 1: per (b,h,chunk) contribution G = (k .* wk)^T v  (64x64)
// ---------------------------------------------------------------------------
#define P1_SMEM_BYTES ((132 + 2 * 128 * 65) * 4)

__global__ __launch_bounds__(256) void wkv_phase1(
    const float* __restrict__ Km, const float* __restrict__ V,
    float* __restrict__ G, const float* __restrict__ tdecay)
{
    extern __shared__ float sm1[];
    float* pw  = sm1;               // decay^i, 0..127
    float* k_s = sm1 + 132;         // [128][65]
    float* v_s = k_s + 128 * 65;

    const int tid = threadIdx.x;
    const int bhn = blockIdx.x;
    const int n = bhn & 31, bh = bhn >> 5;
    const int b = bh >> 4, h = bh & 15;
    const float decay = __expf(-__expf(tdecay[h]));

    for (int i = tid; i < 128; i += 256) pw[i] = powf(decay, (float)i);
    const size_t cbase = (size_t)b * TTT * CC + (size_t)h * HS + (size_t)n * TCH * CC;

    for (int e = tid; e < 128 * 16; e += 256) {
        int i = e >> 4, c4 = (e & 15) * 4;
        size_t gofs = cbase + (size_t)i * CC + c4;
        float4 kv = *(const float4*)(Km + gofs);
        float4 vv = *(const float4*)(V + gofs);
        float* kd = k_s + i * 65 + c4;
        kd[0] = kv.x; kd[1] = kv.y; kd[2] = kv.z; kd[3] = kv.w;
        float* vd = v_s + i * 65 + c4;
        vd[0] = vv.x; vd[1] = vv.y; vd[2] = vv.z; vd[3] = vv.w;
    }
    __syncthreads();

    const int tx = tid & 15, ty = tid >> 4;
    float acc[4][4];
#pragma unroll
    for (int i = 0; i < 4; i++)
#pragma unroll
        for (int j = 0; j < 4; j++) acc[i][j] = 0.f;

    for (int j = 0; j < 128; j++) {
        float wkj = pw[127 - j];
        float kw[4], vv4[4];
#pragma unroll
        for (int q = 0; q < 4; q++) {
            kw[q]  = k_s[j * 65 + ty * 4 + q] * wkj;
            vv4[q] = v_s[j * 65 + tx * 4 + q];
        }
#pragma unroll
        for (int i = 0; i < 4; i++)
#pragma unroll
            for (int c = 0; c < 4; c++)
                acc[i][c] = fmaf(kw[i], vv4[c], acc[i][c]);
    }
    float* Gd = G + (size_t)bhn * (HS * HS);
#pragma unroll
    for (int i = 0; i < 4; i++)
#pragma unroll
        for (int c = 0; c < 4; c++)
            Gd[(ty * 4 + i) * 64 + tx * 4 + c] = acc[i][c];
}

// ---------------------------------------------------------------------------
// 3b) WKV phase 2: in-place scan  buf[n] <- S_n ; S_{n+1} = ws*S_n + G_n
// ---------------------------------------------------------------------------
__global__ __launch_bounds__(256) void wkv_scan(
    float* __restrict__ G, const float* __restrict__ tdecay)
{
    const int tid = threadIdx.x;
    const int bh = blockIdx.x;
    const int h = bh & 15;
    const float decay = __expf(-__expf(tdecay[h]));
    const float ws = powf(decay, 128.f);

    float s[16];
#pragma unroll
    for (int t = 0; t < 16; t++) s[t] = 0.f;

    float* base = G + (size_t)bh * NCH * (HS * HS);
    for (int n = 0; n < NCH; n++) {
        float* p = base + (size_t)n * (HS * HS);
#pragma unroll
        for (int t = 0; t < 16; t++) {
            int idx = tid + t * 256;
            float g = p[idx];
            p[idx] = s[t];
            s[t] = ws * s[t] + g;
        }
    }
}

// ---------------------------------------------------------------------------
// 3c) WKV phase 3: per (b,h,chunk) output
// ---------------------------------------------------------------------------
#define P3_SMEM_BYTES ((132 + 3 * 128 * 65 + 128 * 129 + 64 * 65) * 4)

__global__ __launch_bounds__(256) void wkv_phase3(
    const float* __restrict__ R, const float* __restrict__ Km,
    const float* __restrict__ V, const float* __restrict__ S,
    float* __restrict__ XO,
    const float* __restrict__ tdecay, const float* __restrict__ tfaaaa)
{
    extern __shared__ float sm[];
    float* pw   = sm;
    float* r_s  = sm + 132;
    float* k_s  = r_s + 128 * 65;
    float* v_s  = k_s + 128 * 65;
    float* attS = v_s + 128 * 65;
    float* s_st = attS + 128 * 129;

    const int tid = threadIdx.x;
    const int bhn = blockIdx.x;
    const int n = bhn & 31, bh = bhn >> 5;
    const int b = bh >> 4, h = bh & 15;
    const float decay = __expf(-__expf(tdecay[h]));
    const float u = tfaaaa[h];

    for (int i = tid; i < 128; i += 256) pw[i] = powf(decay, (float)i);

    const float* Sd = S + (size_t)bhn * (HS * HS);
    for (int i = tid; i < 64 * 16; i += 256) {
        int r4 = i >> 4, c4 = (i & 15) * 4;
        float4 sv = *(const float4*)(Sd + r4 * 64 + c4);
        float* d = s_st + r4 * 65 + c4;
        d[0] = sv.x; d[1] = sv.y; d[2] = sv.z; d[3] = sv.w;
    }

    const size_t cbase = (size_t)b * TTT * CC + (size_t)h * HS + (size_t)n * TCH * CC;
    for (int e = tid; e < 128 * 16; e += 256) {
        int i = e >> 4, c4 = (e & 15) * 4;
        size_t gofs = cbase + (size_t)i * CC + c4;
        float4 rv = *(const float4*)(R + gofs);
        float4 kv = *(const float4*)(Km + gofs);
        float4 vv = *(const float4*)(V + gofs);
        float* rd = r_s + i * 65 + c4;
        rd[0] = rv.x; rd[1] = rv.y; rd[2] = rv.z; rd[3] = rv.w;
        float* kd = k_s + i * 65 + c4;
        kd[0] = kv.x; kd[1] = kv.y; kd[2] = kv.z; kd[3] = kv.w;
        float* vd = v_s + i * 65 + c4;
        vd[0] = vv.x; vd[1] = vv.y; vd[2] = vv.z; vd[3] = vv.w;
    }
    __syncthreads();

    const int tx = tid & 15, ty = tid >> 4;

    // att[i][j] = (r_i . k_j) * wmat(i,j)
    {
        float acc[8][8];
#pragma unroll
        for (int i = 0; i < 8; i++)
#pragma unroll
            for (int j = 0; j < 8; j++) acc[i][j] = 0.f;

        for (int kk = 0; kk < 64; kk++) {
            float ra[8], rb[8];
#pragma unroll
            for (int q = 0; q < 4; q++) {
                ra[q]     = r_s[(ty * 4 + q) * 65 + kk];
                ra[4 + q] = r_s[(64 + ty * 4 + q) * 65 + kk];
                rb[q]     = k_s[(tx * 4 + q) * 65 + kk];
                rb[4 + q] = k_s[(64 + tx * 4 + q) * 65 + kk];
            }
#pragma unroll
            for (int i = 0; i < 8; i++)
#pragma unroll
                for (int j = 0; j < 8; j++)
                    acc[i][j] = fmaf(ra[i], rb[j], acc[i][j]);
        }
#pragma unroll
        for (int i = 0; i < 8; i++) {
            int ri = (i < 4) ? (ty * 4 + i) : (64 + ty * 4 + (i - 4));
#pragma unroll
            for (int j = 0; j < 8; j++) {
                int cj = (j < 4) ? (tx * 4 + j) : (64 + tx * 4 + (j - 4));
                int d = ri - cj;
                float w = (d > 0) ? pw[d - 1] : ((d == 0) ? u : 0.f);
                attS[ri * 129 + cj] = acc[i][j] * w;
            }
        }
    }
    __syncthreads();

    // out[i][c] = sum_j att[i][j]*v[j][c] + pw[i]*sum_k r[i][k]*s[k][c]
    {
        float acc2[8][4], acc3[8][4];
#pragma unroll
        for (int i = 0; i < 8; i++)
#pragma unroll
            for (int j = 0; j < 4; j++) { acc2[i][j] = 0.f; acc3[i][j] = 0.f; }

        for (int j = 0; j < 128; j++) {
            float a[8], vv4[4];
#pragma unroll
            for (int q = 0; q < 4; q++) {
                a[q]     = attS[(ty * 4 + q) * 129 + j];
                a[4 + q] = attS[(64 + ty * 4 + q) * 129 + j];
                vv4[q]   = v_s[j * 65 + tx * 4 + q];
            }
#pragma unroll
            for (int i = 0; i < 8; i++)
#pragma unroll
                for (int c = 0; c < 4; c++)
                    acc2[i][c] = fmaf(a[i], vv4[c], acc2[i][c]);
        }
        for (int kk = 0; kk < 64; kk++) {
            float a[8], sv[4];
#pragma unroll
            for (int q = 0; q < 4; q++) {
                a[q]     = r_s[(ty * 4 + q) * 65 + kk];
                a[4 + q] = r_s[(64 + ty * 4 + q) * 65 + kk];
                sv[q]    = s_st[kk * 65 + tx * 4 + q];
            }
#pragma unroll
            for (int i = 0; i < 8; i++)
#pragma unroll
                for (int c = 0; c < 4; c++)
                    acc3[i][c] = fmaf(a[i], sv[c], acc3[i][c]);
        }
#pragma unroll
        for (int i = 0; i < 8; i++) {
            int ri = (i < 4) ? (ty * 4 + i) : (64 + ty * 4 + (i - 4));
            float wbv = pw[ri];
#pragma unroll
            for (int c = 0; c < 4; c++)
                XO[cbase + (size_t)ri * CC + tx * 4 + c] =
                    acc2[i][c] + wbv * acc3[i][c];
        }
    }
}

// ---------------------------------------------------------------------------
// 4) GroupNorm + gate -> bf16 hi/lo output for final GEMM
// ---------------------------------------------------------------------------
__global__ __launch_bounds__(256) void gn_gate_kernel(
    const float* __restrict__ xo, const float* __restrict__ gg,
    const float* __restrict__ lnw, const float* __restrict__ lnb,
    __nv_bfloat16* __restrict__ yg)
{
    int warp = threadIdx.x >> 5, lane = threadIdx.x & 31;
    int gw = blockIdx.x * 8 + warp;   // over MM*HH
    int h = gw % HH;
    int row = gw / HH;
    size_t base = (size_t)row * CC + h * HS;

    float a = xo[base + lane] * 0.125f;
    float b = xo[base + 32 + lane] * 0.125f;
    float s = a + b, ss = a * a + b * b;
#pragma unroll
    for (int o = 16; o > 0; o >>= 1) {
        s  += __shfl_xor_sync(0xffffffffu, s,  o);
        ss += __shfl_xor_sync(0xffffffffu, ss, o);
    }
    float mean = s * (1.f / 64.f);
    float var  = ss * (1.f / 64.f) - mean * mean;
    float inv  = rsqrtf(var + 1e-5f);

    int c0 = h * HS + lane, c1 = c0 + 32;
    float y0 = ((a - mean) * inv * lnw[c0] + lnb[c0]) * gg[base + lane];
    float y1 = ((b - mean) * inv * lnw[c1] + lnb[c1]) * gg[base + 32 + lane];

    size_t b2 = (size_t)row * KD2;
    __nv_bfloat16 h0, l0, h1, l1;
    split_bf16(y0, h0, l0);
    split_bf16(y1, h1, l1);
    yg[b2 + c0]         = h0;
    yg[b2 + c1]         = h1;
    yg[b2 + 1024 + c0]  = l0;
    yg[b2 + 1024 + c1]  = l1;
}

// ---------------------------------------------------------------------------
// Launch
// ---------------------------------------------------------------------------
extern "C" void kernel_launch(void* const* d_in, const int* in_sizes, int n_in,
                              void* d_out, int out_size)
{
    const float* x      = (const float*)d_in[0];
    const float* tmk    = (const float*)d_in[1];
    const float* tmv    = (const float*)d_in[2];
    const float* tmr    = (const float*)d_in[3];
    const float* tmg    = (const float*)d_in[4];
    const float* tdecay = (const float*)d_in[5];
    const float* tfaaaa = (const float*)d_in[6];
    const float* Wr     = (const float*)d_in[7];
    const float* Wk     = (const float*)d_in[8];
    const float* Wv     = (const float*)d_in[9];
    const float* Wg     = (const float*)d_in[10];
    const float* Wo     = (const float*)d_in[11];
    const float* lnw    = (const float*)d_in[12];
    const float* lnb    = (const float*)d_in[13];
    float* out = (float*)d_out;

    __nv_bfloat16 *xr, *xk, *xv, *xg, *ygb, *wr, *wk, *wv, *wg, *wo;
    float *r, *k, *v, *g, *xo, *st;
    cudaGetSymbolAddress((void**)&xr,  g_xr);
    cudaGetSymbolAddress((void**)&xk,  g_xk);
    cudaGetSymbolAddress((void**)&xv,  g_xv);
    cudaGetSymbolAddress((void**)&xg,  g_xg);
    cudaGetSymbolAddress((void**)&ygb, g_ygb);
    cudaGetSymbolAddress((void**)&wr,  g_Wr);
    cudaGetSymbolAddress((void**)&wk,  g_Wk);
    cudaGetSymbolAddress((void**)&wv,  g_Wv);
    cudaGetSymbolAddress((void**)&wg,  g_Wg);
    cudaGetSymbolAddress((void**)&wo,  g_Wo);
    cudaGetSymbolAddress((void**)&r,   g_r);
    cudaGetSymbolAddress((void**)&k,   g_k);
    cudaGetSymbolAddress((void**)&v,   g_v);
    cudaGetSymbolAddress((void**)&g,   g_g);
    cudaGetSymbolAddress((void**)&xo,  g_xo);
    cudaGetSymbolAddress((void**)&st,  g_state);

    cudaFuncSetAttribute(gemm_mma,
                         cudaFuncAttributeMaxDynamicSharedMemorySize, GEMM_SMEM);
    cudaFuncSetAttribute(wkv_phase1,
                         cudaFuncAttributeMaxDynamicSharedMemorySize, P1_SMEM_BYTES);
    cudaFuncSetAttribute(wkv_phase3,
                         cudaFuncAttributeMaxDynamicSharedMemorySize, P3_SMEM_BYTES);

    // 0) weight hi/lo conversion (single launch, 5 weights)
    {
        dim3 cgrid((CC * CC + 255) / 256, 5);
        convw_kernel<<<cgrid, 256>>>(Wr, Wk, Wv, Wg, Wo, wr, wk, wv, wg, wo);
    }

    // 1) mix -> bf16 hi/lo
    {
        int total4 = MM * CC / 4;
        mix_kernel<<<(total4 + 255) / 256, 256>>>(x, tmk, tmv, tmr, tmg,
                                                  xr, xk, xv, xg);
    }

    // 2) projections on tensor cores (mma.sync, 128x256 CTA, 4-stage pipeline)
    dim3 ggrid(CC / 256, MM / 128);   // (4, 128)
    gemm_mma<<<ggrid, 256, GEMM_SMEM>>>(xr, wr, r, 0);
    gemm_mma<<<ggrid, 256, GEMM_SMEM>>>(xk, wk, k, 0);
    gemm_mma<<<ggrid, 256, GEMM_SMEM>>>(xv, wv, v, 0);
    gemm_mma<<<ggrid, 256, GEMM_SMEM>>>(xg, wg, g, 1);   // silu

    // 3) WKV: parallel contributions -> scan -> parallel outputs
    wkv_phase1<<<BB * HH * NCH, 256, P1_SMEM_BYTES>>>(k, v, st, tdecay);
    wkv_scan<<<BB * HH, 256>>>(st, tdecay);
    wkv_phase3<<<BB * HH * NCH, 256, P3_SMEM_BYTES>>>(r, k, v, st, xo,
                                                      tdecay, tfaaaa);

    // 4) GroupNorm + gate -> bf16 hi/lo
    gn_gate_kernel<<<MM * HH / 8, 256>>>(xo, g, lnw, lnb, ygb);

    // 5) output projection (writes d_out)
    gemm_mma<<<ggrid, 256, GEMM_SMEM>>>(ygb, wo, out, 0);
}

// round 7
// speedup vs baseline: 1.4635x; 1.4635x over previous
#include <cuda_runtime.h>
#include <cuda_bf16.h>
#include <cstdint>

// ---------------------------------------------------------------------------
// Problem constants
// ---------------------------------------------------------------------------
#define BB   4
#define TTT  4096
#define CC   1024
#define HH   16
#define HS   64
#define TCH  128
#define NCH  (TTT / TCH)
#define MM   (BB * TTT)      // 16384 rows
#define KD2  2048            // [hi(1024) | lo(1024)] concat width

// ---------------------------------------------------------------------------
// Device scratch (no cudaMalloc allowed)
// ---------------------------------------------------------------------------
__device__ __nv_bfloat16 g_xr[(size_t)MM * KD2];
__device__ __nv_bfloat16 g_xk[(size_t)MM * KD2];
__device__ __nv_bfloat16 g_xv[(size_t)MM * KD2];
__device__ __nv_bfloat16 g_xg[(size_t)MM * KD2];
__device__ __nv_bfloat16 g_ygb[(size_t)MM * KD2];
__device__ __nv_bfloat16 g_Wr[(size_t)CC * KD2];
__device__ __nv_bfloat16 g_Wk[(size_t)CC * KD2];
__device__ __nv_bfloat16 g_Wv[(size_t)CC * KD2];
__device__ __nv_bfloat16 g_Wg[(size_t)CC * KD2];
__device__ __nv_bfloat16 g_Wo[(size_t)CC * KD2];
__device__ float g_r [(size_t)MM * CC];
__device__ float g_k [(size_t)MM * CC];
__device__ float g_v [(size_t)MM * CC];
__device__ float g_g [(size_t)MM * CC];
__device__ float g_xo[(size_t)MM * CC];
__device__ float g_state[(size_t)BB * HH * NCH * HS * HS];  // 33.5 MB

// ---------------------------------------------------------------------------
// Helpers
// ---------------------------------------------------------------------------
__device__ __forceinline__ uint32_t smem_u32(const void* p) {
    uint32_t a;
    asm("{ .reg .u64 t; cvta.to.shared.u64 t, %1; cvt.u32.u64 %0, t; }"
        : "=r"(a) : "l"(p));
    return a;
}

__device__ __forceinline__ void cp_async16(uint32_t dst, const void* src) {
    asm volatile("cp.async.cg.shared.global [%0], [%1], 16;" :: "r"(dst), "l"(src));
}
#define CP_COMMIT() asm volatile("cp.async.commit_group;" ::: "memory")
#define CP_WAIT2()  asm volatile("cp.async.wait_group 2;" ::: "memory")

__device__ __forceinline__ void ldm_x4(uint32_t& r0, uint32_t& r1,
                                       uint32_t& r2, uint32_t& r3, uint32_t addr) {
    asm volatile("ldmatrix.sync.aligned.m8n8.x4.shared.b16 {%0,%1,%2,%3}, [%4];"
                 : "=r"(r0), "=r"(r1), "=r"(r2), "=r"(r3) : "r"(addr));
}

__device__ __forceinline__ void mma_bf16(float& c0, float& c1, float& c2, float& c3,
                                         uint32_t a0, uint32_t a1, uint32_t a2, uint32_t a3,
                                         uint32_t b0, uint32_t b1) {
    asm volatile("mma.sync.aligned.m16n8k16.row.col.f32.bf16.bf16.f32 "
                 "{%0,%1,%2,%3}, {%4,%5,%6,%7}, {%8,%9}, {%0,%1,%2,%3};"
                 : "+f"(c0), "+f"(c1), "+f"(c2), "+f"(c3)
                 : "r"(a0), "r"(a1), "r"(a2), "r"(a3), "r"(b0), "r"(b1));
}

// gemm smem tile: rows x 32 bf16 (64B/row), 16B chunks XOR-swizzled
__device__ __forceinline__ uint32_t swz(int row, int chunk) {
    return (uint32_t)(row * 64 + ((chunk ^ ((row >> 1) & 3)) << 4));
}
// wkv tiles: 128B rows (64 bf16), chunks 0..7
__device__ __forceinline__ uint32_t swzA(int row, int ch) {
    return (uint32_t)(row * 128 + ((ch ^ (row & 7)) << 4));
}
// wkv wide tiles: 256B rows (128 bf16), chunks 0..15 (XOR low 3 bits)
__device__ __forceinline__ uint32_t swzW(int row, int ch) {
    return (uint32_t)(row * 256 + ((ch ^ (row & 7)) << 4));
}

__device__ __forceinline__ void split_bf16(float v, __nv_bfloat16& h, __nv_bfloat16& l) {
    h = __float2bfloat16(v);
    l = __float2bfloat16(v - __bfloat162float(h));
}

union BF4 { __nv_bfloat16 b[4]; uint2 u; };

__device__ __forceinline__ uint32_t pack2(float a, float b) {
    __nv_bfloat162 t = __floats2bfloat162_rn(a, b);
    return *(uint32_t*)&t;
}

// ---------------------------------------------------------------------------
// 0) Weight conversion (all 5 weights in one launch)
// ---------------------------------------------------------------------------
__global__ __launch_bounds__(256) void convw_kernel(
    const float* __restrict__ W0, const float* __restrict__ W1,
    const float* __restrict__ W2, const float* __restrict__ W3,
    const float* __restrict__ W4,
    __nv_bfloat16* __restrict__ o0, __nv_bfloat16* __restrict__ o1,
    __nv_bfloat16* __restrict__ o2, __nv_bfloat16* __restrict__ o3,
    __nv_bfloat16* __restrict__ o4)
{
    const float* W;
    __nv_bfloat16* o;
    switch (blockIdx.y) {
        case 0: W = W0; o = o0; break;
        case 1: W = W1; o = o1; break;
        case 2: W = W2; o = o2; break;
        case 3: W = W3; o = o3; break;
        default: W = W4; o = o4; break;
    }
    int idx = blockIdx.x * 256 + threadIdx.x;
    if (idx >= CC * CC) return;
    int r = idx >> 10, c = idx & 1023;
    __nv_bfloat16 h, l;
    split_bf16(W[idx], h, l);
    o[(size_t)r * KD2 + c] = h;
    o[(size_t)r * KD2 + 1024 + c] = l;
}

// ---------------------------------------------------------------------------
// 1) time-shift + 4-way mix -> bf16 hi/lo outputs
// ---------------------------------------------------------------------------
__global__ __launch_bounds__(256) void mix_kernel(
    const float* __restrict__ x,
    const float* __restrict__ tmk, const float* __restrict__ tmv,
    const float* __restrict__ tmr, const float* __restrict__ tmg,
    __nv_bfloat16* __restrict__ xr, __nv_bfloat16* __restrict__ xk,
    __nv_bfloat16* __restrict__ xv, __nv_bfloat16* __restrict__ xg)
{
    int idx = blockIdx.x * blockDim.x + threadIdx.x;   // float4 index
    const int C4 = CC / 4;
    if (idx >= MM * C4) return;
    int c4 = idx % C4;
    int row = idx / C4;
    int t = row % TTT;

    float4 xc = ((const float4*)x)[idx];
    float4 xp = (t > 0) ? ((const float4*)x)[idx - C4] : make_float4(0.f, 0.f, 0.f, 0.f);

    float4 mk = ((const float4*)tmk)[c4];
    float4 mv = ((const float4*)tmv)[c4];
    float4 mr = ((const float4*)tmr)[c4];
    float4 mg = ((const float4*)tmg)[c4];

    size_t base = (size_t)row * KD2 + c4 * 4;

#define MIXV(out, m)                                                          \
    {                                                                         \
        float o0 = xp.x + m.x * (xc.x - xp.x);                                \
        float o1 = xp.y + m.y * (xc.y - xp.y);                                \
        float o2 = xp.z + m.z * (xc.z - xp.z);                                \
        float o3 = xp.w + m.w * (xc.w - xp.w);                                \
        BF4 hi, lo;                                                           \
        split_bf16(o0, hi.b[0], lo.b[0]);                                     \
        split_bf16(o1, hi.b[1], lo.b[1]);                                     \
        split_bf16(o2, hi.b[2], lo.b[2]);                                     \
        split_bf16(o3, hi.b[3], lo.b[3]);                                     \
        *(uint2*)(out + base) = hi.u;                                         \
        *(uint2*)(out + base + 1024) = lo.u;                                  \
    }
    MIXV(xr, mr); MIXV(xk, mk); MIXV(xv, mv); MIXV(xg, mg);
#undef MIXV
}

// ---------------------------------------------------------------------------
// 2) bf16 mma.sync GEMM (R4 config: 128x128, 4-stage, 2 CTA/SM)
// ---------------------------------------------------------------------------
#define GSTAGES       4
#define GSTAGE_BYTES  16384
#define GEMM_SMEM     (GSTAGES * GSTAGE_BYTES)   // 64 KB

__global__ __launch_bounds__(256, 2) void gemm_mma(
    const __nv_bfloat16* __restrict__ A, const __nv_bfloat16* __restrict__ W,
    float* __restrict__ C, int epi)
{
    extern __shared__ __align__(128) char gsm[];

    const int tid = threadIdx.x;
    const int wid = tid >> 5, lane = tid & 31;
    const int wm = wid & 3;          // 0..3 -> M
    const int wn = wid >> 2;         // 0..1 -> N
    const int m0 = blockIdx.y * 128;
    const int n0 = blockIdx.x * 128;

    const uint32_t sa0 = smem_u32(gsm);

    float acc[2][8][4];
#pragma unroll
    for (int mt = 0; mt < 2; mt++)
#pragma unroll
        for (int nt = 0; nt < 8; nt++)
#pragma unroll
            for (int q = 0; q < 4; q++) acc[mt][nt][q] = 0.f;

    const int lrowA = tid >> 1;                 // 0..127
    const int lcA0 = (tid & 1) * 2;             // chunks {0,1} or {2,3}

    auto load_stage = [&](int s, int buf) {
        int p = s >> 5, kb = s & 31;
        int aoff = (p == 2) ? 1024 : 0;
        int boff = (p == 1) ? 1024 : 0;
        uint32_t ab = sa0 + buf * GSTAGE_BYTES;
        uint32_t bb = ab + 8192;
        const __nv_bfloat16* Ar = A + (size_t)(m0 + lrowA) * KD2 + aoff + kb * 32;
        const __nv_bfloat16* Br = W + (size_t)(n0 + lrowA) * KD2 + boff + kb * 32;
#pragma unroll
        for (int c = 0; c < 2; c++) {
            cp_async16(ab + swz(lrowA, lcA0 + c), Ar + (lcA0 + c) * 8);
            cp_async16(bb + swz(lrowA, lcA0 + c), Br + (lcA0 + c) * 8);
        }
    };

    const int NST = 96;
    load_stage(0, 0); CP_COMMIT();
    load_stage(1, 1); CP_COMMIT();
    load_stage(2, 2); CP_COMMIT();

    for (int s = 0; s < NST; s++) {
        CP_WAIT2();
        __syncthreads();

        if (s + 3 < NST) load_stage(s + 3, (s + 3) & 3);
        CP_COMMIT();

        uint32_t ab = sa0 + (s & 3) * GSTAGE_BYTES;
        uint32_t bb = ab + 8192;
#pragma unroll
        for (int kk = 0; kk < 2; kk++) {
            uint32_t a[2][4];
#pragma unroll
            for (int mt = 0; mt < 2; mt++) {
                int row = wm * 32 + mt * 16 + (lane & 15);
                int ch = kk * 2 + (lane >> 4);
                ldm_x4(a[mt][0], a[mt][1], a[mt][2], a[mt][3], ab + swz(row, ch));
            }
            uint32_t b[8][2];
#pragma unroll
            for (int nq = 0; nq < 4; nq++) {
                int row = wn * 64 + nq * 16 + ((lane >> 4) & 1) * 8 + (lane & 7);
                int ch = kk * 2 + ((lane >> 3) & 1);
                ldm_x4(b[nq * 2][0], b[nq * 2][1], b[nq * 2 + 1][0], b[nq * 2 + 1][1],
                       bb + swz(row, ch));
            }
#pragma unroll
            for (int mt = 0; mt < 2; mt++)
#pragma unroll
                for (int nt = 0; nt < 8; nt++)
                    mma_bf16(acc[mt][nt][0], acc[mt][nt][1], acc[mt][nt][2], acc[mt][nt][3],
                             a[mt][0], a[mt][1], a[mt][2], a[mt][3],
                             b[nt][0], b[nt][1]);
        }
    }

#pragma unroll
    for (int mt = 0; mt < 2; mt++) {
        int gr = m0 + wm * 32 + mt * 16 + (lane >> 2);
#pragma unroll
        for (int nt = 0; nt < 8; nt++) {
            int gc = n0 + wn * 64 + nt * 8 + (lane & 3) * 2;
            float v0 = acc[mt][nt][0], v1 = acc[mt][nt][1];
            float v2 = acc[mt][nt][2], v3 = acc[mt][nt][3];
            if (epi) {
                v0 = v0 / (1.f + expf(-v0));
                v1 = v1 / (1.f + expf(-v1));
                v2 = v2 / (1.f + expf(-v2));
                v3 = v3 / (1.f + expf(-v3));
            }
            *(float2*)&C[(size_t)gr * CC + gc]       = make_float2(v0, v1);
            *(float2*)&C[(size_t)(gr + 8) * CC + gc] = make_float2(v2, v3);
        }
    }
}

// ---------------------------------------------------------------------------
// 3a) WKV phase 1 (tensor): G = (k .* wk)^T v   per (b,h,chunk)
//     M=64 (kc), N=64 (c), K=128 (j).  A = kT (transposed, wk folded), B = vT.
// ---------------------------------------------------------------------------
#define P1_KHI 0
#define P1_KLO 16384
#define P1_VHI 32768
#define P1_VLO 49152
#define P1_PW  65536
#define P1_SMEM (65536 + 640)

__global__ __launch_bounds__(256) void wkv_phase1(
    const float* __restrict__ Km, const float* __restrict__ V,
    float* __restrict__ G, const float* __restrict__ tdecay)
{
    extern __shared__ __align__(128) char sm1c[];
    const uint32_t sb = smem_u32(sm1c);
    float* pw = (float*)(sm1c + P1_PW);

    const int tid = threadIdx.x;
    const int wid = tid >> 5, lane = tid & 31;
    const int bhn = blockIdx.x;
    const int n = bhn & 31, bh = bhn >> 5;
    const int b = bh >> 4, h = bh & 15;
    const float decay = __expf(-__expf(tdecay[h]));

    if (tid < 128) pw[tid] = powf(decay, (float)tid);
    __syncthreads();

    const size_t cbase = (size_t)b * TTT * CC + (size_t)h * HS + (size_t)n * TCH * CC;

    // conversions: kT[kc][j] = k[j][kc] * pw[127-j] (hi/lo), vT[c][j] = v[j][c]
    for (int e = tid; e < 128 * 16; e += 256) {
        int j = e >> 4, c4 = (e & 15) * 4;
        size_t gofs = cbase + (size_t)j * CC + c4;
        float4 kv = *(const float4*)(Km + gofs);
        float4 vv = *(const float4*)(V + gofs);
        float kw = pw[127 - j];
        float ka[4] = {kv.x * kw, kv.y * kw, kv.z * kw, kv.w * kw};
        float va[4] = {vv.x, vv.y, vv.z, vv.w};
        uint32_t co = (uint32_t)((j >> 3));
        uint32_t io = (uint32_t)((j & 7) * 2);
#pragma unroll
        for (int q = 0; q < 4; q++) {
            int c = c4 + q;
            __nv_bfloat16 hh, ll;
            split_bf16(ka[q], hh, ll);
            *(__nv_bfloat16*)(sm1c + P1_KHI + swzW(c, co) + io) = hh;
            *(__nv_bfloat16*)(sm1c + P1_KLO + swzW(c, co) + io) = ll;
            split_bf16(va[q], hh, ll);
            *(__nv_bfloat16*)(sm1c + P1_VHI + swzW(c, co) + io) = hh;
            *(__nv_bfloat16*)(sm1c + P1_VLO + swzW(c, co) + io) = ll;
        }
    }
    __syncthreads();

    // GEMM: warps 4M x 2N, warp tile 16x32
    const int wm = wid & 3;      // 16 rows each
    const int wn = wid >> 2;     // 32 cols each
    float acc[4][4];
#pragma unroll
    for (int nt = 0; nt < 4; nt++)
#pragma unroll
        for (int q = 0; q < 4; q++) acc[nt][q] = 0.f;

#pragma unroll
    for (int pass = 0; pass < 3; pass++) {
        uint32_t Ab = sb + ((pass == 2) ? P1_KLO : P1_KHI);
        uint32_t Bb = sb + ((pass == 1) ? P1_VLO : P1_VHI);
#pragma unroll
        for (int kk = 0; kk < 8; kk++) {
            uint32_t a[4];
            {
                int row = wm * 16 + (lane & 15);
                int ch = kk * 2 + (lane >> 4);
                ldm_x4(a[0], a[1], a[2], a[3], Ab + swzW(row, ch));
            }
            uint32_t bfr[4][2];
#pragma unroll
            for (int nq = 0; nq < 2; nq++) {
                int row = wn * 32 + nq * 16 + ((lane >> 4) & 1) * 8 + (lane & 7);
                int ch = kk * 2 + ((lane >> 3) & 1);
                ldm_x4(bfr[nq * 2][0], bfr[nq * 2][1],
                       bfr[nq * 2 + 1][0], bfr[nq * 2 + 1][1], Bb + swzW(row, ch));
            }
#pragma unroll
            for (int nt = 0; nt < 4; nt++)
                mma_bf16(acc[nt][0], acc[nt][1], acc[nt][2], acc[nt][3],
                         a[0], a[1], a[2], a[3], bfr[nt][0], bfr[nt][1]);
        }
    }

    float* Gd = G + (size_t)bhn * (HS * HS);
    int i = wm * 16 + (lane >> 2);
#pragma unroll
    for (int nt = 0; nt < 4; nt++) {
        int c = wn * 32 + nt * 8 + (lane & 3) * 2;
        *(float2*)&Gd[i * 64 + c]       = make_float2(acc[nt][0], acc[nt][1]);
        *(float2*)&Gd[(i + 8) * 64 + c] = make_float2(acc[nt][2], acc[nt][3]);
    }
}

// ---------------------------------------------------------------------------
// 3b) WKV phase 2: in-place scan  buf[n] <- S_n ; S_{n+1} = ws*S_n + G_n
// ---------------------------------------------------------------------------
__global__ __launch_bounds__(256) void wkv_scan(
    float* __restrict__ G, const float* __restrict__ tdecay)
{
    const int tid = threadIdx.x;
    const int bh = blockIdx.x;
    const int h = bh & 15;
    const float decay = __expf(-__expf(tdecay[h]));
    const float ws = powf(decay, 128.f);

    float s[16];
#pragma unroll
    for (int t = 0; t < 16; t++) s[t] = 0.f;

    float* base = G + (size_t)bh * NCH * (HS * HS);
    for (int n = 0; n < NCH; n++) {
        float* p = base + (size_t)n * (HS * HS);
#pragma unroll
        for (int t = 0; t < 16; t++) {
            int idx = tid + t * 256;
            float g = p[idx];
            p[idx] = s[t];
            s[t] = ws * s[t] + g;
        }
    }
}

// ---------------------------------------------------------------------------
// 3c) WKV phase 3 (tensor): out = (r k^T .* w) v + (r S) .* wb   per chunk
// ---------------------------------------------------------------------------
#define PH3_RHI 0
#define PH3_RLO 16384
#define PH3_KHI 32768
#define PH3_KLO 49152
#define PH3_VHI 65536
#define PH3_VLO 81920
#define PH3_SHI 98304
#define PH3_SLO 106496
#define PH3_AHI 114688
#define PH3_ALO 147456
#define PH3_PW  180224
#define PH3_SMEM (180224 + 640)

__global__ __launch_bounds__(256) void wkv_phase3(
    const float* __restrict__ R, const float* __restrict__ Km,
    const float* __restrict__ V, const float* __restrict__ S,
    float* __restrict__ XO,
    const float* __restrict__ tdecay, const float* __restrict__ tfaaaa)
{
    extern __shared__ __align__(128) char smc[];
    const uint32_t sb = smem_u32(smc);
    float* pw = (float*)(smc + PH3_PW);

    const int tid = threadIdx.x;
    const int wid = tid >> 5, lane = tid & 31;
    const int bhn = blockIdx.x;
    const int n = bhn & 31, bh = bhn >> 5;
    const int b = bh >> 4, h = bh & 15;
    const float decay = __expf(-__expf(tdecay[h]));
    const float u = tfaaaa[h];

    if (tid < 128) pw[tid] = powf(decay, (float)tid);

    const size_t cbase = (size_t)b * TTT * CC + (size_t)h * HS + (size_t)n * TCH * CC;

    // conversions: r,k -> [128][64] tiles (hi/lo); v -> vT [64][128]
    for (int e = tid; e < 128 * 16; e += 256) {
        int row = e >> 4, c4 = (e & 15) * 4;
        size_t gofs = cbase + (size_t)row * CC + c4;
        float4 rv = *(const float4*)(R + gofs);
        float4 kv = *(const float4*)(Km + gofs);
        float4 vv = *(const float4*)(V + gofs);
        // r, k direct (row-major, 128B rows)
        uint32_t off = swzA(row, c4 >> 3) + (c4 & 7) * 2;
        BF4 hi, lo;
        split_bf16(rv.x, hi.b[0], lo.b[0]); split_bf16(rv.y, hi.b[1], lo.b[1]);
        split_bf16(rv.z, hi.b[2], lo.b[2]); split_bf16(rv.w, hi.b[3], lo.b[3]);
        *(uint2*)(smc + PH3_RHI + off) = hi.u;
        *(uint2*)(smc + PH3_RLO + off) = lo.u;
        split_bf16(kv.x, hi.b[0], lo.b[0]); split_bf16(kv.y, hi.b[1], lo.b[1]);
        split_bf16(kv.z, hi.b[2], lo.b[2]); split_bf16(kv.w, hi.b[3], lo.b[3]);
        *(uint2*)(smc + PH3_KHI + off) = hi.u;
        *(uint2*)(smc + PH3_KLO + off) = lo.u;
        // v transposed
        float va[4] = {vv.x, vv.y, vv.z, vv.w};
        uint32_t co = (uint32_t)(row >> 3);
        uint32_t io = (uint32_t)((row & 7) * 2);
#pragma unroll
        for (int q = 0; q < 4; q++) {
            int c = c4 + q;
            __nv_bfloat16 hh, ll;
            split_bf16(va[q], hh, ll);
            *(__nv_bfloat16*)(smc + PH3_VHI + swzW(c, co) + io) = hh;
            *(__nv_bfloat16*)(smc + PH3_VLO + swzW(c, co) + io) = ll;
        }
    }
    // sT[c][kk] = S[kk][c]  (64x64, 128B rows)
    {
        const float* Sd = S + (size_t)bhn * (HS * HS);
        for (int e = tid; e < 64 * 16; e += 256) {
            int kkr = e >> 4, c4 = (e & 15) * 4;
            float4 sv = *(const float4*)(Sd + kkr * 64 + c4);
            float sa[4] = {sv.x, sv.y, sv.z, sv.w};
            uint32_t co = (uint32_t)(kkr >> 3);
            uint32_t io = (uint32_t)((kkr & 7) * 2);
#pragma unroll
            for (int q = 0; q < 4; q++) {
                int c = c4 + q;
                __nv_bfloat16 hh, ll;
                split_bf16(sa[q], hh, ll);
                *(__nv_bfloat16*)(smc + PH3_SHI + swzA(c, co) + io) = hh;
                *(__nv_bfloat16*)(smc + PH3_SLO + swzA(c, co) + io) = ll;
            }
        }
    }
    __syncthreads();

    // ---- ATT GEMM: att = r k^T  (M=128,N=128,K=64), warps 4M x 2N (32x64)
    {
        const int wm = wid & 3, wn = wid >> 2;
        float acc[2][8][4];
#pragma unroll
        for (int mt = 0; mt < 2; mt++)
#pragma unroll
            for (int nt = 0; nt < 8; nt++)
#pragma unroll
                for (int q = 0; q < 4; q++) acc[mt][nt][q] = 0.f;

#pragma unroll
        for (int pass = 0; pass < 3; pass++) {
            uint32_t Ab = sb + ((pass == 2) ? PH3_RLO : PH3_RHI);
            uint32_t Bb = sb + ((pass == 1) ? PH3_KLO : PH3_KHI);
#pragma unroll
            for (int kk = 0; kk < 4; kk++) {
                uint32_t a[2][4];
#pragma unroll
                for (int mt = 0; mt < 2; mt++) {
                    int row = wm * 32 + mt * 16 + (lane & 15);
                    int ch = kk * 2 + (lane >> 4);
                    ldm_x4(a[mt][0], a[mt][1], a[mt][2], a[mt][3], Ab + swzA(row, ch));
                }
                uint32_t bfr[8][2];
#pragma unroll
                for (int nq = 0; nq < 4; nq++) {
                    int row = wn * 64 + nq * 16 + ((lane >> 4) & 1) * 8 + (lane & 7);
                    int ch = kk * 2 + ((lane >> 3) & 1);
                    ldm_x4(bfr[nq * 2][0], bfr[nq * 2][1],
                           bfr[nq * 2 + 1][0], bfr[nq * 2 + 1][1], Bb + swzA(row, ch));
                }
#pragma unroll
                for (int mt = 0; mt < 2; mt++)
#pragma unroll
                    for (int nt = 0; nt < 8; nt++)
                        mma_bf16(acc[mt][nt][0], acc[mt][nt][1], acc[mt][nt][2], acc[mt][nt][3],
                                 a[mt][0], a[mt][1], a[mt][2], a[mt][3],
                                 bfr[nt][0], bfr[nt][1]);
            }
        }

        // apply w-mask and store att hi/lo to smem
#pragma unroll
        for (int mt = 0; mt < 2; mt++) {
            int i0 = wm * 32 + mt * 16 + (lane >> 2);
#pragma unroll
            for (int nt = 0; nt < 8; nt++) {
                int j0 = wn * 64 + nt * 8 + (lane & 3) * 2;
#pragma unroll
                for (int rr = 0; rr < 2; rr++) {
                    int i = i0 + rr * 8;
                    float av0 = acc[mt][nt][rr * 2 + 0];
                    float av1 = acc[mt][nt][rr * 2 + 1];
                    int d0 = i - j0, d1 = i - (j0 + 1);
                    float w0 = (d0 > 0) ? pw[d0 - 1] : ((d0 == 0) ? u : 0.f);
                    float w1 = (d1 > 0) ? pw[d1 - 1] : ((d1 == 0) ? u : 0.f);
                    float v0 = av0 * w0, v1 = av1 * w1;
                    __nv_bfloat16 h0, l0, h1, l1;
                    split_bf16(v0, h0, l0);
                    split_bf16(v1, h1, l1);
                    uint32_t off = swzW(i, j0 >> 3) + (j0 & 7) * 2;
                    *(uint32_t*)(smc + PH3_AHI + off) =
                        ((uint32_t)*(uint16_t*)&h1 << 16) | *(uint16_t*)&h0;
                    *(uint32_t*)(smc + PH3_ALO + off) =
                        ((uint32_t)*(uint16_t*)&l1 << 16) | *(uint16_t*)&l0;
                }
            }
        }
    }
    __syncthreads();

    // ---- OUT GEMMs: acc2 = att @ v (K=128), acc3 = r @ S (K=64)
    {
        const int wm = wid & 3, wn = wid >> 2;   // 32 rows, 32 cols
        float acc2[2][4][4], acc3[2][4][4];
#pragma unroll
        for (int mt = 0; mt < 2; mt++)
#pragma unroll
            for (int nt = 0; nt < 4; nt++)
#pragma unroll
                for (int q = 0; q < 4; q++) { acc2[mt][nt][q] = 0.f; acc3[mt][nt][q] = 0.f; }

#pragma unroll
        for (int pass = 0; pass < 3; pass++) {
            uint32_t Ab = sb + ((pass == 2) ? PH3_ALO : PH3_AHI);
            uint32_t Bb = sb + ((pass == 1) ? PH3_VLO : PH3_VHI);
#pragma unroll
            for (int kk = 0; kk < 8; kk++) {
                uint32_t a[2][4];
#pragma unroll
                for (int mt = 0; mt < 2; mt++) {
                    int row = wm * 32 + mt * 16 + (lane & 15);
                    int ch = kk * 2 + (lane >> 4);
                    ldm_x4(a[mt][0], a[mt][1], a[mt][2], a[mt][3], Ab + swzW(row, ch));
                }
                uint32_t bfr[4][2];
#pragma unroll
                for (int nq = 0; nq < 2; nq++) {
                    int row = wn * 32 + nq * 16 + ((lane >> 4) & 1) * 8 + (lane & 7);
                    int ch = kk * 2 + ((lane >> 3) & 1);
                    ldm_x4(bfr[nq * 2][0], bfr[nq * 2][1],
                           bfr[nq * 2 + 1][0], bfr[nq * 2 + 1][1], Bb + swzW(row, ch));
                }
#pragma unroll
                for (int mt = 0; mt < 2; mt++)
#pragma unroll
                    for (int nt = 0; nt < 4; nt++)
                        mma_bf16(acc2[mt][nt][0], acc2[mt][nt][1], acc2[mt][nt][2], acc2[mt][nt][3],
                                 a[mt][0], a[mt][1], a[mt][2], a[mt][3],
                                 bfr[nt][0], bfr[nt][1]);
            }
        }
#pragma unroll
        for (int pass = 0; pass < 3; pass++) {
            uint32_t Ab = sb + ((pass == 2) ? PH3_RLO : PH3_RHI);
            uint32_t Bb = sb + ((pass == 1) ? PH3_SLO : PH3_SHI);
#pragma unroll
            for (int kk = 0; kk < 4; kk++) {
                uint32_t a[2][4];
#pragma unroll
                for (int mt = 0; mt < 2; mt++) {
                    int row = wm * 32 + mt * 16 + (lane & 15);
                    int ch = kk * 2 + (lane >> 4);
                    ldm_x4(a[mt][0], a[mt][1], a[mt][2], a[mt][3], Ab + swzA(row, ch));
                }
                uint32_t bfr[4][2];
#pragma unroll
                for (int nq = 0; nq < 2; nq++) {
                    int row = wn * 32 + nq * 16 + ((lane >> 4) & 1) * 8 + (lane & 7);
                    int ch = kk * 2 + ((lane >> 3) & 1);
                    ldm_x4(bfr[nq * 2][0], bfr[nq * 2][1],
                           bfr[nq * 2 + 1][0], bfr[nq * 2 + 1][1], Bb + swzA(row, ch));
                }
#pragma unroll
                for (int mt = 0; mt < 2; mt++)
#pragma unroll
                    for (int nt = 0; nt < 4; nt++)
                        mma_bf16(acc3[mt][nt][0], acc3[mt][nt][1], acc3[mt][nt][2], acc3[mt][nt][3],
                                 a[mt][0], a[mt][1], a[mt][2], a[mt][3],
                                 bfr[nt][0], bfr[nt][1]);
            }
        }

        // epilogue: out = acc2 + wb[i] * acc3
#pragma unroll
        for (int mt = 0; mt < 2; mt++) {
            int i0 = wm * 32 + mt * 16 + (lane >> 2);
#pragma unroll
            for (int nt = 0; nt < 4; nt++) {
                int c = wn * 32 + nt * 8 + (lane & 3) * 2;
                float wb0 = pw[i0], wb1 = pw[i0 + 8];
                *(float2*)&XO[cbase + (size_t)i0 * CC + c] =
                    make_float2(acc2[mt][nt][0] + wb0 * acc3[mt][nt][0],
                                acc2[mt][nt][1] + wb0 * acc3[mt][nt][1]);
                *(float2*)&XO[cbase + (size_t)(i0 + 8) * CC + c] =
                    make_float2(acc2[mt][nt][2] + wb1 * acc3[mt][nt][2],
                                acc2[mt][nt][3] + wb1 * acc3[mt][nt][3]);
            }
        }
    }
}

// ---------------------------------------------------------------------------
// 4) GroupNorm + gate -> bf16 hi/lo output for final GEMM
// ---------------------------------------------------------------------------
__global__ __launch_bounds__(256) void gn_gate_kernel(
    const float* __restrict__ xo, const float* __restrict__ gg,
    const float* __restrict__ lnw, const float* __restrict__ lnb,
    __nv_bfloat16* __restrict__ yg)
{
    int warp = threadIdx.x >> 5, lane = threadIdx.x & 31;
    int gw = blockIdx.x * 8 + warp;   // over MM*HH
    int h = gw % HH;
    int row = gw / HH;
    size_t base = (size_t)row * CC + h * HS;

    float a = xo[base + lane] * 0.125f;
    float b = xo[base + 32 + lane] * 0.125f;
    float s = a + b, ss = a * a + b * b;
#pragma unroll
    for (int o = 16; o > 0; o >>= 1) {
        s  += __shfl_xor_sync(0xffffffffu, s,  o);
        ss += __shfl_xor_sync(0xffffffffu, ss, o);
    }
    float mean = s * (1.f / 64.f);
    float var  = ss * (1.f / 64.f) - mean * mean;
    float inv  = rsqrtf(var + 1e-5f);

    int c0 = h * HS + lane, c1 = c0 + 32;
    float y0 = ((a - mean) * inv * lnw[c0] + lnb[c0]) * gg[base + lane];
    float y1 = ((b - mean) * inv * lnw[c1] + lnb[c1]) * gg[base + 32 + lane];

    size_t b2 = (size_t)row * KD2;
    __nv_bfloat16 h0, l0, h1, l1;
    split_bf16(y0, h0, l0);
    split_bf16(y1, h1, l1);
    yg[b2 + c0]         = h0;
    yg[b2 + c1]         = h1;
    yg[b2 + 1024 + c0]  = l0;
    yg[b2 + 1024 + c1]  = l1;
}

// ---------------------------------------------------------------------------
// Launch
// ---------------------------------------------------------------------------
extern "C" void kernel_launch(void* const* d_in, const int* in_sizes, int n_in,
                              void* d_out, int out_size)
{
    const float* x      = (const float*)d_in[0];
    const float* tmk    = (const float*)d_in[1];
    const float* tmv    = (const float*)d_in[2];
    const float* tmr    = (const float*)d_in[3];
    const float* tmg    = (const float*)d_in[4];
    const float* tdecay = (const float*)d_in[5];
    const float* tfaaaa = (const float*)d_in[6];
    const float* Wr     = (const float*)d_in[7];
    const float* Wk     = (const float*)d_in[8];
    const float* Wv     = (const float*)d_in[9];
    const float* Wg     = (const float*)d_in[10];
    const float* Wo     = (const float*)d_in[11];
    const float* lnw    = (const float*)d_in[12];
    const float* lnb    = (const float*)d_in[13];
    float* out = (float*)d_out;

    __nv_bfloat16 *xr, *xk, *xv, *xg, *ygb, *wr, *wk, *wv, *wg, *wo;
    float *r, *k, *v, *g, *xo, *st;
    cudaGetSymbolAddress((void**)&xr,  g_xr);
    cudaGetSymbolAddress((void**)&xk,  g_xk);
    cudaGetSymbolAddress((void**)&xv,  g_xv);
    cudaGetSymbolAddress((void**)&xg,  g_xg);
    cudaGetSymbolAddress((void**)&ygb, g_ygb);
    cudaGetSymbolAddress((void**)&wr,  g_Wr);
    cudaGetSymbolAddress((void**)&wk,  g_Wk);
    cudaGetSymbolAddress((void**)&wv,  g_Wv);
    cudaGetSymbolAddress((void**)&wg,  g_Wg);
    cudaGetSymbolAddress((void**)&wo,  g_Wo);
    cudaGetSymbolAddress((void**)&r,   g_r);
    cudaGetSymbolAddress((void**)&k,   g_k);
    cudaGetSymbolAddress((void**)&v,   g_v);
    cudaGetSymbolAddress((void**)&g,   g_g);
    cudaGetSymbolAddress((void**)&xo,  g_xo);
    cudaGetSymbolAddress((void**)&st,  g_state);

    cudaFuncSetAttribute(gemm_mma,
                         cudaFuncAttributeMaxDynamicSharedMemorySize, GEMM_SMEM);
    cudaFuncSetAttribute(wkv_phase1,
                         cudaFuncAttributeMaxDynamicSharedMemorySize, P1_SMEM);
    cudaFuncSetAttribute(wkv_phase3,
                         cudaFuncAttributeMaxDynamicSharedMemorySize, PH3_SMEM);

    // 0) weight hi/lo conversion (single launch, 5 weights)
    {
        dim3 cgrid((CC * CC + 255) / 256, 5);
        convw_kernel<<<cgrid, 256>>>(Wr, Wk, Wv, Wg, Wo, wr, wk, wv, wg, wo);
    }

    // 1) mix -> bf16 hi/lo
    {
        int total4 = MM * CC / 4;
        mix_kernel<<<(total4 + 255) / 256, 256>>>(x, tmk, tmv, tmr, tmg,
                                                  xr, xk, xv, xg);
    }

    // 2) projections on tensor cores (mma.sync, R4 config)
    dim3 ggrid(CC / 128, MM / 128);   // (8, 128)
    gemm_mma<<<ggrid, 256, GEMM_SMEM>>>(xr, wr, r, 0);
    gemm_mma<<<ggrid, 256, GEMM_SMEM>>>(xk, wk, k, 0);
    gemm_mma<<<ggrid, 256, GEMM_SMEM>>>(xv, wv, v, 0);
    gemm_mma<<<ggrid, 256, GEMM_SMEM>>>(xg, wg, g, 1);   // silu

    // 3) WKV on tensor cores: contributions -> scan -> outputs
    wkv_phase1<<<BB * HH * NCH, 256, P1_SMEM>>>(k, v, st, tdecay);
    wkv_scan<<<BB * HH, 256>>>(st, tdecay);
    wkv_phase3<<<BB * HH * NCH, 256, PH3_SMEM>>>(r, k, v, st, xo,
                                                 tdecay, tfaaaa);

    // 4) GroupNorm + gate -> bf16 hi/lo
    gn_gate_kernel<<<MM * HH / 8, 256>>>(xo, g, lnw, lnb, ygb);

    // 5) output projection (writes d_out)
    gemm_mma<<<ggrid, 256, GEMM_SMEM>>>(ygb, wo, out, 0);
}

// round 11
// speedup vs baseline: 1.9306x; 1.3192x over previous
#include <cuda_runtime.h>
#include <cuda_bf16.h>
#include <cuda_fp16.h>
#include <cstdint>

// ---------------------------------------------------------------------------
// Problem constants
// ---------------------------------------------------------------------------
#define BB   4
#define TTT  4096
#define CC   1024
#define HH   16
#define HS   64
#define TCH  128
#define NCH  (TTT / TCH)
#define MM   (BB * TTT)      // 16384 rows
#define KD2  2048            // [hi(1024) | lo(1024)] weight concat width

// ---------------------------------------------------------------------------
// Device scratch (no cudaMalloc allowed)
// ---------------------------------------------------------------------------
__device__ __half g_xr[(size_t)MM * CC];
__device__ __half g_xk[(size_t)MM * CC];
__device__ __half g_xv[(size_t)MM * CC];
__device__ __half g_xg[(size_t)MM * CC];
__device__ __half g_ygb[(size_t)MM * CC];
__device__ __half g_Wr[(size_t)CC * KD2];
__device__ __half g_Wk[(size_t)CC * KD2];
__device__ __half g_Wv[(size_t)CC * KD2];
__device__ __half g_Wg[(size_t)CC * KD2];
__device__ __half g_Wo[(size_t)CC * KD2];
__device__ float g_r [(size_t)MM * CC];
__device__ float g_k [(size_t)MM * CC];
__device__ float g_v [(size_t)MM * CC];
__device__ float g_g [(size_t)MM * CC];
__device__ float g_xo[(size_t)MM * CC];
__device__ float g_state[(size_t)BB * HH * NCH * HS * HS];  // 33.5 MB

// ---------------------------------------------------------------------------
// Helpers
// ---------------------------------------------------------------------------
__device__ __forceinline__ uint32_t smem_u32(const void* p) {
    uint32_t a;
    asm("{ .reg .u64 t; cvta.to.shared.u64 t, %1; cvt.u32.u64 %0, t; }"
        : "=r"(a) : "l"(p));
    return a;
}

__device__ __forceinline__ void cp_async16(uint32_t dst, const void* src) {
    asm volatile("cp.async.cg.shared.global [%0], [%1], 16;" :: "r"(dst), "l"(src));
}
#define CP_COMMIT() asm volatile("cp.async.commit_group;" ::: "memory")
#define CP_WAIT2()  asm volatile("cp.async.wait_group 2;" ::: "memory")

__device__ __forceinline__ void ldm_x4(uint32_t& r0, uint32_t& r1,
                                       uint32_t& r2, uint32_t& r3, uint32_t addr) {
    asm volatile("ldmatrix.sync.aligned.m8n8.x4.shared.b16 {%0,%1,%2,%3}, [%4];"
                 : "=r"(r0), "=r"(r1), "=r"(r2), "=r"(r3) : "r"(addr));
}

__device__ __forceinline__ void mma_bf16(float& c0, float& c1, float& c2, float& c3,
                                         uint32_t a0, uint32_t a1, uint32_t a2, uint32_t a3,
                                         uint32_t b0, uint32_t b1) {
    asm volatile("mma.sync.aligned.m16n8k16.row.col.f32.bf16.bf16.f32 "
                 "{%0,%1,%2,%3}, {%4,%5,%6,%7}, {%8,%9}, {%0,%1,%2,%3};"
                 : "+f"(c0), "+f"(c1), "+f"(c2), "+f"(c3)
                 : "r"(a0), "r"(a1), "r"(a2), "r"(a3), "r"(b0), "r"(b1));
}

__device__ __forceinline__ void mma_fp16(float& c0, float& c1, float& c2, float& c3,
                                         uint32_t a0, uint32_t a1, uint32_t a2, uint32_t a3,
                                         uint32_t b0, uint32_t b1) {
    asm volatile("mma.sync.aligned.m16n8k16.row.col.f32.f16.f16.f32 "
                 "{%0,%1,%2,%3}, {%4,%5,%6,%7}, {%8,%9}, {%0,%1,%2,%3};"
                 : "+f"(c0), "+f"(c1), "+f"(c2), "+f"(c3)
                 : "r"(a0), "r"(a1), "r"(a2), "r"(a3), "r"(b0), "r"(b1));
}

// gemm smem tile: rows x 32 elems (64B/row), 16B chunks XOR-swizzled
__device__ __forceinline__ uint32_t swz(int row, int chunk) {
    return (uint32_t)(row * 64 + ((chunk ^ ((row >> 1) & 3)) << 4));
}
// wkv tiles: 128B rows (64 bf16), chunks 0..7
__device__ __forceinline__ uint32_t swzA(int row, int ch) {
    return (uint32_t)(row * 128 + ((ch ^ (row & 7)) << 4));
}
// wkv wide tiles: 256B rows (128 bf16), chunks 0..15
__device__ __forceinline__ uint32_t swzW(int row, int ch) {
    return (uint32_t)(row * 256 + ((ch ^ (row & 7)) << 4));
}

__device__ __forceinline__ void split_bf16(float v, __nv_bfloat16& h, __nv_bfloat16& l) {
    h = __float2bfloat16(v);
    l = __float2bfloat16(v - __bfloat162float(h));
}
__device__ __forceinline__ void split_h(float v, __half& h, __half& l) {
    h = __float2half_rn(v);
    l = __float2half_rn(v - __half2float(h));
}

union BF4 { __nv_bfloat16 b[4]; uint2 u; };
union HF4 { __half h[4]; uint2 u; };

// ---------------------------------------------------------------------------
// 0) Weight conversion (all 5): W (CC x CC fp32) -> [hi | lo] fp16 (CC x KD2)
// ---------------------------------------------------------------------------
__global__ __launch_bounds__(256) void convw_kernel(
    const float* __restrict__ W0, const float* __restrict__ W1,
    const float* __restrict__ W2, const float* __restrict__ W3,
    const float* __restrict__ W4,
    __half* __restrict__ o0, __half* __restrict__ o1,
    __half* __restrict__ o2, __half* __restrict__ o3,
    __half* __restrict__ o4)
{
    const float* W;
    __half* o;
    switch (blockIdx.y) {
        case 0: W = W0; o = o0; break;
        case 1: W = W1; o = o1; break;
        case 2: W = W2; o = o2; break;
        case 3: W = W3; o = o3; break;
        default: W = W4; o = o4; break;
    }
    int idx = blockIdx.x * 256 + threadIdx.x;
    if (idx >= CC * CC) return;
    int r = idx >> 10, c = idx & 1023;
    __half h, l;
    split_h(W[idx], h, l);
    o[(size_t)r * KD2 + c] = h;
    o[(size_t)r * KD2 + 1024 + c] = l;
}

// ---------------------------------------------------------------------------
// 1) time-shift + 4-way mix -> fp16 outputs (unsplit)
// ---------------------------------------------------------------------------
__global__ __launch_bounds__(256) void mix_kernel(
    const float* __restrict__ x,
    const float* __restrict__ tmk, const float* __restrict__ tmv,
    const float* __restrict__ tmr, const float* __restrict__ tmg,
    __half* __restrict__ xr, __half* __restrict__ xk,
    __half* __restrict__ xv, __half* __restrict__ xg)
{
    int idx = blockIdx.x * blockDim.x + threadIdx.x;   // float4 index
    const int C4 = CC / 4;
    if (idx >= MM * C4) return;
    int c4 = idx % C4;
    int row = idx / C4;
    int t = row % TTT;

    float4 xc = ((const float4*)x)[idx];
    float4 xp = (t > 0) ? ((const float4*)x)[idx - C4] : make_float4(0.f, 0.f, 0.f, 0.f);

    float4 mk = ((const float4*)tmk)[c4];
    float4 mv = ((const float4*)tmv)[c4];
    float4 mr = ((const float4*)tmr)[c4];
    float4 mg = ((const float4*)tmg)[c4];

#define MIXV(out, m)                                                          \
    {                                                                         \
        HF4 o;                                                                \
        o.h[0] = __float2half_rn(xp.x + m.x * (xc.x - xp.x));                 \
        o.h[1] = __float2half_rn(xp.y + m.y * (xc.y - xp.y));                 \
        o.h[2] = __float2half_rn(xp.z + m.z * (xc.z - xp.z));                 \
        o.h[3] = __float2half_rn(xp.w + m.w * (xc.w - xp.w));                 \
        *(uint2*)(out + (size_t)row * CC + c4 * 4) = o.u;                     \
    }
    MIXV(xr, mr); MIXV(xk, mk); MIXV(xv, mv); MIXV(xg, mg);
#undef MIXV
}

// ---------------------------------------------------------------------------
// 2) fp16 mma.sync GEMM: C = A @ (Whi+Wlo)^T   (2 passes, f32 accum)
//    CTA 128x128, BK=32, 8 warps (4M x 2N), 4-stage cp.async, 2 CTA/SM.
// ---------------------------------------------------------------------------
#define GSTAGES       4
#define GSTAGE_BYTES  16384
#define GEMM_SMEM     (GSTAGES * GSTAGE_BYTES)   // 64 KB

__global__ __launch_bounds__(256, 2) void gemm_mma(
    const __half* __restrict__ A, const __half* __restrict__ W,
    float* __restrict__ C, int epi)
{
    extern __shared__ __align__(128) char gsm[];

    const int tid = threadIdx.x;
    const int wid = tid >> 5, lane = tid & 31;
    const int wm = wid & 3;
    const int wn = wid >> 2;
    const int m0 = blockIdx.y * 128;
    const int n0 = blockIdx.x * 128;

    const uint32_t sa0 = smem_u32(gsm);

    float acc[2][8][4];
#pragma unroll
    for (int mt = 0; mt < 2; mt++)
#pragma unroll
        for (int nt = 0; nt < 8; nt++)
#pragma unroll
            for (int q = 0; q < 4; q++) acc[mt][nt][q] = 0.f;

    const int lrowA = tid >> 1;                 // 0..127
    const int lcA0 = (tid & 1) * 2;             // chunks {0,1} or {2,3}

    auto load_stage = [&](int s, int buf) {
        int p = s >> 5, kb = s & 31;            // p: 0=Whi, 1=Wlo
        int boff = p ? 1024 : 0;
        uint32_t ab = sa0 + buf * GSTAGE_BYTES;
        uint32_t bb = ab + 8192;
        const __half* Ar = A + (size_t)(m0 + lrowA) * CC + kb * 32;
        const __half* Br = W + (size_t)(n0 + lrowA) * KD2 + boff + kb * 32;
#pragma unroll
        for (int c = 0; c < 2; c++) {
            cp_async16(ab + swz(lrowA, lcA0 + c), Ar + (lcA0 + c) * 8);
            cp_async16(bb + swz(lrowA, lcA0 + c), Br + (lcA0 + c) * 8);
        }
    };

    const int NST = 64;                          // 2 passes x 32 k-blocks
    load_stage(0, 0); CP_COMMIT();
    load_stage(1, 1); CP_COMMIT();
    load_stage(2, 2); CP_COMMIT();

    for (int s = 0; s < NST; s++) {
        CP_WAIT2();
        __syncthreads();

        if (s + 3 < NST) load_stage(s + 3, (s + 3) & 3);
        CP_COMMIT();

        uint32_t ab = sa0 + (s & 3) * GSTAGE_BYTES;
        uint32_t bb = ab + 8192;
#pragma unroll
        for (int kk = 0; kk < 2; kk++) {
            uint32_t a[2][4];
#pragma unroll
            for (int mt = 0; mt < 2; mt++) {
                int row = wm * 32 + mt * 16 + (lane & 15);
                int ch = kk * 2 + (lane >> 4);
                ldm_x4(a[mt][0], a[mt][1], a[mt][2], a[mt][3], ab + swz(row, ch));
            }
            uint32_t b[8][2];
#pragma unroll
            for (int nq = 0; nq < 4; nq++) {
                int row = wn * 64 + nq * 16 + ((lane >> 4) & 1) * 8 + (lane & 7);
                int ch = kk * 2 + ((lane >> 3) & 1);
                ldm_x4(b[nq * 2][0], b[nq * 2][1], b[nq * 2 + 1][0], b[nq * 2 + 1][1],
                       bb + swz(row, ch));
            }
#pragma unroll
            for (int mt = 0; mt < 2; mt++)
#pragma unroll
                for (int nt = 0; nt < 8; nt++)
                    mma_fp16(acc[mt][nt][0], acc[mt][nt][1], acc[mt][nt][2], acc[mt][nt][3],
                             a[mt][0], a[mt][1], a[mt][2], a[mt][3],
                             b[nt][0], b[nt][1]);
        }
    }

#pragma unroll
    for (int mt = 0; mt < 2; mt++) {
        int gr = m0 + wm * 32 + mt * 16 + (lane >> 2);
#pragma unroll
        for (int nt = 0; nt < 8; nt++) {
            int gc = n0 + wn * 64 + nt * 8 + (lane & 3) * 2;
            float v0 = acc[mt][nt][0], v1 = acc[mt][nt][1];
            float v2 = acc[mt][nt][2], v3 = acc[mt][nt][3];
            if (epi) {
                v0 = v0 / (1.f + expf(-v0));
                v1 = v1 / (1.f + expf(-v1));
                v2 = v2 / (1.f + expf(-v2));
                v3 = v3 / (1.f + expf(-v3));
            }
            *(float2*)&C[(size_t)gr * CC + gc]       = make_float2(v0, v1);
            *(float2*)&C[(size_t)(gr + 8) * CC + gc] = make_float2(v2, v3);
        }
    }
}

// ---------------------------------------------------------------------------
// 3a) WKV phase 1 (tensor, bf16x3): G = (k .* wk)^T v   per (b,h,chunk)
// ---------------------------------------------------------------------------
#define P1_KHI 0
#define P1_KLO 16384
#define P1_VHI 32768
#define P1_VLO 49152
#define P1_PW  65536
#define P1_SMEM (65536 + 640)

__global__ __launch_bounds__(256) void wkv_phase1(
    const float* __restrict__ Km, const float* __restrict__ V,
    float* __restrict__ G, const float* __restrict__ tdecay)
{
    extern __shared__ __align__(128) char sm1c[];
    const uint32_t sb = smem_u32(sm1c);
    float* pw = (float*)(sm1c + P1_PW);

    const int tid = threadIdx.x;
    const int wid = tid >> 5, lane = tid & 31;
    const int bhn = blockIdx.x;
    const int n = bhn & 31, bh = bhn >> 5;
    const int b = bh >> 4, h = bh & 15;
    const float decay = __expf(-__expf(tdecay[h]));

    if (tid < 128) pw[tid] = powf(decay, (float)tid);
    __syncthreads();

    const size_t cbase = (size_t)b * TTT * CC + (size_t)h * HS + (size_t)n * TCH * CC;

    for (int e = tid; e < 128 * 16; e += 256) {
        int j = e >> 4, c4 = (e & 15) * 4;
        size_t gofs = cbase + (size_t)j * CC + c4;
        float4 kv = *(const float4*)(Km + gofs);
        float4 vv = *(const float4*)(V + gofs);
        float kw = pw[127 - j];
        float ka[4] = {kv.x * kw, kv.y * kw, kv.z * kw, kv.w * kw};
        float va[4] = {vv.x, vv.y, vv.z, vv.w};
        uint32_t co = (uint32_t)((j >> 3));
        uint32_t io = (uint32_t)((j & 7) * 2);
#pragma unroll
        for (int q = 0; q < 4; q++) {
            int c = c4 + q;
            __nv_bfloat16 hh, ll;
            split_bf16(ka[q], hh, ll);
            *(__nv_bfloat16*)(sm1c + P1_KHI + swzW(c, co) + io) = hh;
            *(__nv_bfloat16*)(sm1c + P1_KLO + swzW(c, co) + io) = ll;
            split_bf16(va[q], hh, ll);
            *(__nv_bfloat16*)(sm1c + P1_VHI + swzW(c, co) + io) = hh;
            *(__nv_bfloat16*)(sm1c + P1_VLO + swzW(c, co) + io) = ll;
        }
    }
    __syncthreads();

    const int wm = wid & 3;
    const int wn = wid >> 2;
    float acc[4][4];
#pragma unroll
    for (int nt = 0; nt < 4; nt++)
#pragma unroll
        for (int q = 0; q < 4; q++) acc[nt][q] = 0.f;

#pragma unroll
    for (int pass = 0; pass < 3; pass++) {
        uint32_t Ab = sb + ((pass == 2) ? P1_KLO : P1_KHI);
        uint32_t Bb = sb + ((pass == 1) ? P1_VLO : P1_VHI);
#pragma unroll
        for (int kk = 0; kk < 8; kk++) {
            uint32_t a[4];
            {
                int row = wm * 16 + (lane & 15);
                int ch = kk * 2 + (lane >> 4);
                ldm_x4(a[0], a[1], a[2], a[3], Ab + swzW(row, ch));
            }
            uint32_t bfr[4][2];
#pragma unroll
            for (int nq = 0; nq < 2; nq++) {
                int row = wn * 32 + nq * 16 + ((lane >> 4) & 1) * 8 + (lane & 7);
                int ch = kk * 2 + ((lane >> 3) & 1);
                ldm_x4(bfr[nq * 2][0], bfr[nq * 2][1],
                       bfr[nq * 2 + 1][0], bfr[nq * 2 + 1][1], Bb + swzW(row, ch));
            }
#pragma unroll
            for (int nt = 0; nt < 4; nt++)
                mma_bf16(acc[nt][0], acc[nt][1], acc[nt][2], acc[nt][3],
                         a[0], a[1], a[2], a[3], bfr[nt][0], bfr[nt][1]);
        }
    }

    float* Gd = G + (size_t)bhn * (HS * HS);
    int i = wm * 16 + (lane >> 2);
#pragma unroll
    for (int nt = 0; nt < 4; nt++) {
        int c = wn * 32 + nt * 8 + (lane & 3) * 2;
        *(float2*)&Gd[i * 64 + c]       = make_float2(acc[nt][0], acc[nt][1]);
        *(float2*)&Gd[(i + 8) * 64 + c] = make_float2(acc[nt][2], acc[nt][3]);
    }
}

// ---------------------------------------------------------------------------
// 3b) WKV phase 2: in-place scan
// ---------------------------------------------------------------------------
__global__ __launch_bounds__(256) void wkv_scan(
    float* __restrict__ G, const float* __restrict__ tdecay)
{
    const int tid = threadIdx.x;
    const int bh = blockIdx.x;
    const int h = bh & 15;
    const float decay = __expf(-__expf(tdecay[h]));
    const float ws = powf(decay, 128.f);

    float s[16];
#pragma unroll
    for (int t = 0; t < 16; t++) s[t] = 0.f;

    float* base = G + (size_t)bh * NCH * (HS * HS);
    for (int n = 0; n < NCH; n++) {
        float* p = base + (size_t)n * (HS * HS);
#pragma unroll
        for (int t = 0; t < 16; t++) {
            int idx = tid + t * 256;
            float g = p[idx];
            p[idx] = s[t];
            s[t] = ws * s[t] + g;
        }
    }
}

// ---------------------------------------------------------------------------
// 3c) WKV phase 3 (tensor, bf16x3): out = (r k^T .* w) v + (r S) .* wb
// ---------------------------------------------------------------------------
#define PH3_RHI 0
#define PH3_RLO 16384
#define PH3_KHI 32768
#define PH3_KLO 49152
#define PH3_VHI 65536
#define PH3_VLO 81920
#define PH3_SHI 98304
#define PH3_SLO 106496
#define PH3_AHI 114688
#define PH3_ALO 147456
#define PH3_PW  180224
#define PH3_SMEM (180224 + 640)

__global__ __launch_bounds__(256) void wkv_phase3(
    const float* __restrict__ R, const float* __restrict__ Km,
    const float* __restrict__ V, const float* __restrict__ S,
    float* __restrict__ XO,
    const float* __restrict__ tdecay, const float* __restrict__ tfaaaa)
{
    extern __shared__ __align__(128) char smc[];
    const uint32_t sb = smem_u32(smc);
    float* pw = (float*)(smc + PH3_PW);

    const int tid = threadIdx.x;
    const int wid = tid >> 5, lane = tid & 31;
    const int bhn = blockIdx.x;
    const int n = bhn & 31, bh = bhn >> 5;
    const int b = bh >> 4, h = bh & 15;
    const float decay = __expf(-__expf(tdecay[h]));
    const float u = tfaaaa[h];

    if (tid < 128) pw[tid] = powf(decay, (float)tid);

    const size_t cbase = (size_t)b * TTT * CC + (size_t)h * HS + (size_t)n * TCH * CC;

    for (int e = tid; e < 128 * 16; e += 256) {
        int row = e >> 4, c4 = (e & 15) * 4;
        size_t gofs = cbase + (size_t)row * CC + c4;
        float4 rv = *(const float4*)(R + gofs);
        float4 kv = *(const float4*)(Km + gofs);
        float4 vv = *(const float4*)(V + gofs);
        uint32_t off = swzA(row, c4 >> 3) + (c4 & 7) * 2;
        BF4 hi, lo;
        split_bf16(rv.x, hi.b[0], lo.b[0]); split_bf16(rv.y, hi.b[1], lo.b[1]);
        split_bf16(rv.z, hi.b[2], lo.b[2]); split_bf16(rv.w, hi.b[3], lo.b[3]);
        *(uint2*)(smc + PH3_RHI + off) = hi.u;
        *(uint2*)(smc + PH3_RLO + off) = lo.u;
        split_bf16(kv.x, hi.b[0], lo.b[0]); split_bf16(kv.y, hi.b[1], lo.b[1]);
        split_bf16(kv.z, hi.b[2], lo.b[2]); split_bf16(kv.w, hi.b[3], lo.b[3]);
        *(uint2*)(smc + PH3_KHI + off) = hi.u;
        *(uint2*)(smc + PH3_KLO + off) = lo.u;
        float va[4] = {vv.x, vv.y, vv.z, vv.w};
        uint32_t co = (uint32_t)(row >> 3);
        uint32_t io = (uint32_t)((row & 7) * 2);
#pragma unroll
        for (int q = 0; q < 4; q++) {
            int c = c4 + q;
            __nv_bfloat16 hh, ll;
            split_bf16(va[q], hh, ll);
            *(__nv_bfloat16*)(smc + PH3_VHI + swzW(c, co) + io) = hh;
            *(__nv_bfloat16*)(smc + PH3_VLO + swzW(c, co) + io) = ll;
        }
    }
    {
        const float* Sd = S + (size_t)bhn * (HS * HS);
        for (int e = tid; e < 64 * 16; e += 256) {
            int kkr = e >> 4, c4 = (e & 15) * 4;
            float4 sv = *(const float4*)(Sd + kkr * 64 + c4);
            float sa[4] = {sv.x, sv.y, sv.z, sv.w};
            uint32_t co = (uint32_t)(kkr >> 3);
            uint32_t io = (uint32_t)((kkr & 7) * 2);
#pragma unroll
            for (int q = 0; q < 4; q++) {
                int c = c4 + q;
                __nv_bfloat16 hh, ll;
                split_bf16(sa[q], hh, ll);
                *(__nv_bfloat16*)(smc + PH3_SHI + swzA(c, co) + io) = hh;
                *(__nv_bfloat16*)(smc + PH3_SLO + swzA(c, co) + io) = ll;
            }
        }
    }
    __syncthreads();

    {
        const int wm = wid & 3, wn = wid >> 2;
        float acc[2][8][4];
#pragma unroll
        for (int mt = 0; mt < 2; mt++)
#pragma unroll
            for (int nt = 0; nt < 8; nt++)
#pragma unroll
                for (int q = 0; q < 4; q++) acc[mt][nt][q] = 0.f;

#pragma unroll
        for (int pass = 0; pass < 3; pass++) {
            uint32_t Ab = sb + ((pass == 2) ? PH3_RLO : PH3_RHI);
            uint32_t Bb = sb + ((pass == 1) ? PH3_KLO : PH3_KHI);
#pragma unroll
            for (int kk = 0; kk < 4; kk++) {
                uint32_t a[2][4];
#pragma unroll
                for (int mt = 0; mt < 2; mt++) {
                    int row = wm * 32 + mt * 16 + (lane & 15);
                    int ch = kk * 2 + (lane >> 4);
                    ldm_x4(a[mt][0], a[mt][1], a[mt][2], a[mt][3], Ab + swzA(row, ch));
                }
                uint32_t bfr[8][2];
#pragma unroll
                for (int nq = 0; nq < 4; nq++) {
                    int row = wn * 64 + nq * 16 + ((lane >> 4) & 1) * 8 + (lane & 7);
                    int ch = kk * 2 + ((lane >> 3) & 1);
                    ldm_x4(bfr[nq * 2][0], bfr[nq * 2][1],
                           bfr[nq * 2 + 1][0], bfr[nq * 2 + 1][1], Bb + swzA(row, ch));
                }
#pragma unroll
                for (int mt = 0; mt < 2; mt++)
#pragma unroll
                    for (int nt = 0; nt < 8; nt++)
                        mma_bf16(acc[mt][nt][0], acc[mt][nt][1], acc[mt][nt][2], acc[mt][nt][3],
                                 a[mt][0], a[mt][1], a[mt][2], a[mt][3],
                                 bfr[nt][0], bfr[nt][1]);
            }
        }

#pragma unroll
        for (int mt = 0; mt < 2; mt++) {
            int i0 = wm * 32 + mt * 16 + (lane >> 2);
#pragma unroll
            for (int nt = 0; nt < 8; nt++) {
                int j0 = wn * 64 + nt * 8 + (lane & 3) * 2;
#pragma unroll
                for (int rr = 0; rr < 2; rr++) {
                    int i = i0 + rr * 8;
                    float av0 = acc[mt][nt][rr * 2 + 0];
                    float av1 = acc[mt][nt][rr * 2 + 1];
                    int d0 = i - j0, d1 = i - (j0 + 1);
                    float w0 = (d0 > 0) ? pw[d0 - 1] : ((d0 == 0) ? u : 0.f);
                    float w1 = (d1 > 0) ? pw[d1 - 1] : ((d1 == 0) ? u : 0.f);
                    float v0 = av0 * w0, v1 = av1 * w1;
                    __nv_bfloat16 h0, l0, h1, l1;
                    split_bf16(v0, h0, l0);
                    split_bf16(v1, h1, l1);
                    uint32_t off = swzW(i, j0 >> 3) + (j0 & 7) * 2;
                    *(uint32_t*)(smc + PH3_AHI + off) =
                        ((uint32_t)*(uint16_t*)&h1 << 16) | *(uint16_t*)&h0;
                    *(uint32_t*)(smc + PH3_ALO + off) =
                        ((uint32_t)*(uint16_t*)&l1 << 16) | *(uint16_t*)&l0;
                }
            }
        }
    }
    __syncthreads();

    {
        const int wm = wid & 3, wn = wid >> 2;
        float acc2[2][4][4], acc3[2][4][4];
#pragma unroll
        for (int mt = 0; mt < 2; mt++)
#pragma unroll
            for (int nt = 0; nt < 4; nt++)
#pragma unroll
                for (int q = 0; q < 4; q++) { acc2[mt][nt][q] = 0.f; acc3[mt][nt][q] = 0.f; }

#pragma unroll
        for (int pass = 0; pass < 3; pass++) {
            uint32_t Ab = sb + ((pass == 2) ? PH3_ALO : PH3_AHI);
            uint32_t Bb = sb + ((pass == 1) ? PH3_VLO : PH3_VHI);
#pragma unroll
            for (int kk = 0; kk < 8; kk++) {
                uint32_t a[2][4];
#pragma unroll
                for (int mt = 0; mt < 2; mt++) {
                    int row = wm * 32 + mt * 16 + (lane & 15);
                    int ch = kk * 2 + (lane >> 4);
                    ldm_x4(a[mt][0], a[mt][1], a[mt][2], a[mt][3], Ab + swzW(row, ch));
                }
                uint32_t bfr[4][2];
#pragma unroll
                for (int nq = 0; nq < 2; nq++) {
                    int row = wn * 32 + nq * 16 + ((lane >> 4) & 1) * 8 + (lane & 7);
                    int ch = kk * 2 + ((lane >> 3) & 1);
                    ldm_x4(bfr[nq * 2][0], bfr[nq * 2][1],
                           bfr[nq * 2 + 1][0], bfr[nq * 2 + 1][1], Bb + swzW(row, ch));
                }
#pragma unroll
                for (int mt = 0; mt < 2; mt++)
#pragma unroll
                    for (int nt = 0; nt < 4; nt++)
                        mma_bf16(acc2[mt][nt][0], acc2[mt][nt][1], acc2[mt][nt][2], acc2[mt][nt][3],
                                 a[mt][0], a[mt][1], a[mt][2], a[mt][3],
                                 bfr[nt][0], bfr[nt][1]);
            }
        }
#pragma unroll
        for (int pass = 0; pass < 3; pass++) {
            uint32_t Ab = sb + ((pass == 2) ? PH3_RLO : PH3_RHI);
            uint32_t Bb = sb + ((pass == 1) ? PH3_SLO : PH3_SHI);
#pragma unroll
            for (int kk = 0; kk < 4; kk++) {
                uint32_t a[2][4];
#pragma unroll
                for (int mt = 0; mt < 2; mt++) {
                    int row = wm * 32 + mt * 16 + (lane & 15);
                    int ch = kk * 2 + (lane >> 4);
                    ldm_x4(a[mt][0], a[mt][1], a[mt][2], a[mt][3], Ab + swzA(row, ch));
                }
                uint32_t bfr[4][2];
#pragma unroll
                for (int nq = 0; nq < 2; nq++) {
                    int row = wn * 32 + nq * 16 + ((lane >> 4) & 1) * 8 + (lane & 7);
                    int ch = kk * 2 + ((lane >> 3) & 1);
                    ldm_x4(bfr[nq * 2][0], bfr[nq * 2][1],
                           bfr[nq * 2 + 1][0], bfr[nq * 2 + 1][1], Bb + swzA(row, ch));
                }
#pragma unroll
                for (int mt = 0; mt < 2; mt++)
#pragma unroll
                    for (int nt = 0; nt < 4; nt++)
                        mma_bf16(acc3[mt][nt][0], acc3[mt][nt][1], acc3[mt][nt][2], acc3[mt][nt][3],
                                 a[mt][0], a[mt][1], a[mt][2], a[mt][3],
                                 bfr[nt][0], bfr[nt][1]);
            }
        }

#pragma unroll
        for (int mt = 0; mt < 2; mt++) {
            int i0 = wm * 32 + mt * 16 + (lane >> 2);
#pragma unroll
            for (int nt = 0; nt < 4; nt++) {
                int c = wn * 32 + nt * 8 + (lane & 3) * 2;
                float wb0 = pw[i0], wb1 = pw[i0 + 8];
                *(float2*)&XO[cbase + (size_t)i0 * CC + c] =
                    make_float2(acc2[mt][nt][0] + wb0 * acc3[mt][nt][0],
                                acc2[mt][nt][1] + wb0 * acc3[mt][nt][1]);
                *(float2*)&XO[cbase + (size_t)(i0 + 8) * CC + c] =
                    make_float2(acc2[mt][nt][2] + wb1 * acc3[mt][nt][2],
                                acc2[mt][nt][3] + wb1 * acc3[mt][nt][3]);
            }
        }
    }
}

// ---------------------------------------------------------------------------
// 4) GroupNorm + gate -> fp16 output for final GEMM
// ---------------------------------------------------------------------------
__global__ __launch_bounds__(256) void gn_gate_kernel(
    const float* __restrict__ xo, const float* __restrict__ gg,
    const float* __restrict__ lnw, const float* __restrict__ lnb,
    __half* __restrict__ yg)
{
    int warp = threadIdx.x >> 5, lane = threadIdx.x & 31;
    int gw = blockIdx.x * 8 + warp;   // over MM*HH
    int h = gw % HH;
    int row = gw / HH;
    size_t base = (size_t)row * CC + h * HS;

    float a = xo[base + lane] * 0.125f;
    float b = xo[base + 32 + lane] * 0.125f;
    float s = a + b, ss = a * a + b * b;
#pragma unroll
    for (int o = 16; o > 0; o >>= 1) {
        s  += __shfl_xor_sync(0xffffffffu, s,  o);
        ss += __shfl_xor_sync(0xffffffffu, ss, o);
    }
    float mean = s * (1.f / 64.f);
    float var  = ss * (1.f / 64.f) - mean * mean;
    float inv  = rsqrtf(var + 1e-5f);

    int c0 = h * HS + lane, c1 = c0 + 32;
    float y0 = ((a - mean) * inv * lnw[c0] + lnb[c0]) * gg[base + lane];
    float y1 = ((b - mean) * inv * lnw[c1] + lnb[c1]) * gg[base + 32 + lane];

    yg[base + lane]      = __float2half_rn(y0);
    yg[base + 32 + lane] = __float2half_rn(y1);
}

// ---------------------------------------------------------------------------
// Launch
// ---------------------------------------------------------------------------
extern "C" void kernel_launch(void* const* d_in, const int* in_sizes, int n_in,
                              void* d_out, int out_size)
{
    const float* x      = (const float*)d_in[0];
    const float* tmk    = (const float*)d_in[1];
    const float* tmv    = (const float*)d_in[2];
    const float* tmr    = (const float*)d_in[3];
    const float* tmg    = (const float*)d_in[4];
    const float* tdecay = (const float*)d_in[5];
    const float* tfaaaa = (const float*)d_in[6];
    const float* Wr     = (const float*)d_in[7];
    const float* Wk     = (const float*)d_in[8];
    const float* Wv     = (const float*)d_in[9];
    const float* Wg     = (const float*)d_in[10];
    const float* Wo     = (const float*)d_in[11];
    const float* lnw    = (const float*)d_in[12];
    const float* lnb    = (const float*)d_in[13];
    float* out = (float*)d_out;

    __half *xr, *xk, *xv, *xg, *ygb, *wr, *wk, *wv, *wg, *wo;
    float *r, *k, *v, *g, *xo, *st;
    cudaGetSymbolAddress((void**)&xr,  g_xr);
    cudaGetSymbolAddress((void**)&xk,  g_xk);
    cudaGetSymbolAddress((void**)&xv,  g_xv);
    cudaGetSymbolAddress((void**)&xg,  g_xg);
    cudaGetSymbolAddress((void**)&ygb, g_ygb);
    cudaGetSymbolAddress((void**)&wr,  g_Wr);
    cudaGetSymbolAddress((void**)&wk,  g_Wk);
    cudaGetSymbolAddress((void**)&wv,  g_Wv);
    cudaGetSymbolAddress((void**)&wg,  g_Wg);
    cudaGetSymbolAddress((void**)&wo,  g_Wo);
    cudaGetSymbolAddress((void**)&r,   g_r);
    cudaGetSymbolAddress((void**)&k,   g_k);
    cudaGetSymbolAddress((void**)&v,   g_v);
    cudaGetSymbolAddress((void**)&g,   g_g);
    cudaGetSymbolAddress((void**)&xo,  g_xo);
    cudaGetSymbolAddress((void**)&st,  g_state);

    cudaFuncSetAttribute(gemm_mma,
                         cudaFuncAttributeMaxDynamicSharedMemorySize, GEMM_SMEM);
    cudaFuncSetAttribute(wkv_phase1,
                         cudaFuncAttributeMaxDynamicSharedMemorySize, P1_SMEM);
    cudaFuncSetAttribute(wkv_phase3,
                         cudaFuncAttributeMaxDynamicSharedMemorySize, PH3_SMEM);

    // 0) weight hi/lo fp16 conversion (single launch, 5 weights)
    {
        dim3 cgrid((CC * CC + 255) / 256, 5);
        convw_kernel<<<cgrid, 256>>>(Wr, Wk, Wv, Wg, Wo, wr, wk, wv, wg, wo);
    }

    // 1) mix -> fp16
    {
        int total4 = MM * CC / 4;
        mix_kernel<<<(total4 + 255) / 256, 256>>>(x, tmk, tmv, tmr, tmg,
                                                  xr, xk, xv, xg);
    }

    // 2) projections (fp16 2-pass mma.sync)
    dim3 ggrid(CC / 128, MM / 128);   // (8, 128)
    gemm_mma<<<ggrid, 256, GEMM_SMEM>>>(xr, wr, r, 0);
    gemm_mma<<<ggrid, 256, GEMM_SMEM>>>(xk, wk, k, 0);
    gemm_mma<<<ggrid, 256, GEMM_SMEM>>>(xv, wv, v, 0);
    gemm_mma<<<ggrid, 256, GEMM_SMEM>>>(xg, wg, g, 1);   // silu

    // 3) WKV on tensor cores (bf16x3, unchanged)
    wkv_phase1<<<BB * HH * NCH, 256, P1_SMEM>>>(k, v, st, tdecay);
    wkv_scan<<<BB * HH, 256>>>(st, tdecay);
    wkv_phase3<<<BB * HH * NCH, 256, PH3_SMEM>>>(r, k, v, st, xo,
                                                 tdecay, tfaaaa);

    // 4) GroupNorm + gate -> fp16
    gn_gate_kernel<<<MM * HH / 8, 256>>>(xo, g, lnw, lnb, ygb);

    // 5) output projection (writes d_out)
    gemm_mma<<<ggrid, 256, GEMM_SMEM>>>(ygb, wo, out, 0);
}

// round 15
// speedup vs baseline: 2.4422x; 1.2650x over previous
#include <cuda_runtime.h>
#include <cuda_bf16.h>
#include <cuda_fp16.h>
#include <cstdint>

// ---------------------------------------------------------------------------
// Problem constants
// ---------------------------------------------------------------------------
#define BB   4
#define TTT  4096
#define CC   1024
#define HH   16
#define HS   64
#define TCH  128
#define NCH  (TTT / TCH)
#define MM   (BB * TTT)      // 16384 rows
#define KD2  2048            // [hi(1024) | lo(1024)] weight concat width

// ---------------------------------------------------------------------------
// Device scratch (no cudaMalloc allowed)
// ---------------------------------------------------------------------------
__device__ __half g_xr[(size_t)MM * CC];
__device__ __half g_xk[(size_t)MM * CC];
__device__ __half g_xv[(size_t)MM * CC];
__device__ __half g_xg[(size_t)MM * CC];
__device__ __half g_ygb[(size_t)MM * CC];
__device__ __half g_Wr[(size_t)CC * KD2];
__device__ __half g_Wk[(size_t)CC * KD2];
__device__ __half g_Wv[(size_t)CC * KD2];
__device__ __half g_Wg[(size_t)CC * KD2];
__device__ __half g_Wo[(size_t)CC * KD2];
__device__ __half g_r [(size_t)MM * CC];
__device__ __half g_k [(size_t)MM * CC];
__device__ __half g_v [(size_t)MM * CC];
__device__ __half g_g [(size_t)MM * CC];
__device__ float g_state[(size_t)BB * HH * NCH * HS * HS];  // 33.5 MB

// ---------------------------------------------------------------------------
// Helpers
// ---------------------------------------------------------------------------
__device__ __forceinline__ uint32_t smem_u32(const void* p) {
    uint32_t a;
    asm("{ .reg .u64 t; cvta.to.shared.u64 t, %1; cvt.u32.u64 %0, t; }"
        : "=r"(a) : "l"(p));
    return a;
}

__device__ __forceinline__ void cp_async16(uint32_t dst, const void* src) {
    asm volatile("cp.async.cg.shared.global [%0], [%1], 16;" :: "r"(dst), "l"(src));
}
#define CP_COMMIT() asm volatile("cp.async.commit_group;" ::: "memory")
#define CP_WAIT2()  asm volatile("cp.async.wait_group 2;" ::: "memory")

__device__ __forceinline__ void ldm_x4(uint32_t& r0, uint32_t& r1,
                                       uint32_t& r2, uint32_t& r3, uint32_t addr) {
    asm volatile("ldmatrix.sync.aligned.m8n8.x4.shared.b16 {%0,%1,%2,%3}, [%4];"
                 : "=r"(r0), "=r"(r1), "=r"(r2), "=r"(r3) : "r"(addr));
}

__device__ __forceinline__ void mma_fp16(float& c0, float& c1, float& c2, float& c3,
                                         uint32_t a0, uint32_t a1, uint32_t a2, uint32_t a3,
                                         uint32_t b0, uint32_t b1) {
    asm volatile("mma.sync.aligned.m16n8k16.row.col.f32.f16.f16.f32 "
                 "{%0,%1,%2,%3}, {%4,%5,%6,%7}, {%8,%9}, {%0,%1,%2,%3};"
                 : "+f"(c0), "+f"(c1), "+f"(c2), "+f"(c3)
                 : "r"(a0), "r"(a1), "r"(a2), "r"(a3), "r"(b0), "r"(b1));
}

// gemm smem tile: rows x 32 elems (64B/row), 16B chunks XOR-swizzled
__device__ __forceinline__ uint32_t swz(int row, int chunk) {
    return (uint32_t)(row * 64 + ((chunk ^ ((row >> 1) & 3)) << 4));
}
// wkv tiles: 128B rows (64 fp16), chunks 0..7
__device__ __forceinline__ uint32_t swzA(int row, int ch) {
    return (uint32_t)(row * 128 + ((ch ^ (row & 7)) << 4));
}
// wkv wide tiles: 256B rows (128 fp16), chunks 0..15
__device__ __forceinline__ uint32_t swzW(int row, int ch) {
    return (uint32_t)(row * 256 + ((ch ^ (row & 7)) << 4));
}

__device__ __forceinline__ void split_h(float v, __half& h, __half& l) {
    h = __float2half_rn(v);
    l = __float2half_rn(v - __half2float(h));
}

__device__ __forceinline__ uint32_t pack2h(float a, float b) {
    __half2 t = __floats2half2_rn(a, b);
    return *(uint32_t*)&t;
}

union HF4 { __half h[4]; uint2 u; };
union HF8 { __half h[8]; uint4 u; };

// ---------------------------------------------------------------------------
// 0) Weight conversion (all 5): W (CC x CC fp32) -> [hi | lo] fp16 (CC x KD2)
// ---------------------------------------------------------------------------
__global__ __launch_bounds__(256) void convw_kernel(
    const float* __restrict__ W0, const float* __restrict__ W1,
    const float* __restrict__ W2, const float* __restrict__ W3,
    const float* __restrict__ W4,
    __half* __restrict__ o0, __half* __restrict__ o1,
    __half* __restrict__ o2, __half* __restrict__ o3,
    __half* __restrict__ o4)
{
    const float* W;
    __half* o;
    switch (blockIdx.y) {
        case 0: W = W0; o = o0; break;
        case 1: W = W1; o = o1; break;
        case 2: W = W2; o = o2; break;
        case 3: W = W3; o = o3; break;
        default: W = W4; o = o4; break;
    }
    int idx = blockIdx.x * 256 + threadIdx.x;
    if (idx >= CC * CC) return;
    int r = idx >> 10, c = idx & 1023;
    __half h, l;
    split_h(W[idx], h, l);
    o[(size_t)r * KD2 + c] = h;
    o[(size_t)r * KD2 + 1024 + c] = l;
}

// ---------------------------------------------------------------------------
// 1) time-shift + 4-way mix -> fp16 outputs
// ---------------------------------------------------------------------------
__global__ __launch_bounds__(256) void mix_kernel(
    const float* __restrict__ x,
    const float* __restrict__ tmk, const float* __restrict__ tmv,
    const float* __restrict__ tmr, const float* __restrict__ tmg,
    __half* __restrict__ xr, __half* __restrict__ xk,
    __half* __restrict__ xv, __half* __restrict__ xg)
{
    int idx = blockIdx.x * blockDim.x + threadIdx.x;   // float4 index
    const int C4 = CC / 4;
    if (idx >= MM * C4) return;
    int c4 = idx % C4;
    int row = idx / C4;
    int t = row % TTT;

    float4 xc = ((const float4*)x)[idx];
    float4 xp = (t > 0) ? ((const float4*)x)[idx - C4] : make_float4(0.f, 0.f, 0.f, 0.f);

    float4 mk = ((const float4*)tmk)[c4];
    float4 mv = ((const float4*)tmv)[c4];
    float4 mr = ((const float4*)tmr)[c4];
    float4 mg = ((const float4*)tmg)[c4];

#define MIXV(out, m)                                                          \
    {                                                                         \
        HF4 o;                                                                \
        o.h[0] = __float2half_rn(xp.x + m.x * (xc.x - xp.x));                 \
        o.h[1] = __float2half_rn(xp.y + m.y * (xc.y - xp.y));                 \
        o.h[2] = __float2half_rn(xp.z + m.z * (xc.z - xp.z));                 \
        o.h[3] = __float2half_rn(xp.w + m.w * (xc.w - xp.w));                 \
        *(uint2*)(out + (size_t)row * CC + c4 * 4) = o.u;                     \
    }
    MIXV(xr, mr); MIXV(xk, mk); MIXV(xv, mv); MIXV(xg, mg);
#undef MIXV
}

// ---------------------------------------------------------------------------
// 2) fp16 mma.sync GEMM: C = A @ (Whi+Wlo)^T   (2 passes, f32 accum)
//    CTA 128x128, BK=32, 8 warps (4M x 2N), 4-stage cp.async, 2 CTA/SM.
//    epi: 0 = fp32 out, 1 = silu + fp16 out, 2 = fp16 out
// ---------------------------------------------------------------------------
#define GSTAGES       4
#define GSTAGE_BYTES  16384
#define GEMM_SMEM     (GSTAGES * GSTAGE_BYTES)   // 64 KB

__global__ __launch_bounds__(256, 2) void gemm_mma(
    const __half* __restrict__ A, const __half* __restrict__ W,
    void* __restrict__ Cout, int epi)
{
    extern __shared__ __align__(128) char gsm[];

    const int tid = threadIdx.x;
    const int wid = tid >> 5, lane = tid & 31;
    const int wm = wid & 3;
    const int wn = wid >> 2;
    const int m0 = blockIdx.y * 128;
    const int n0 = blockIdx.x * 128;

    const uint32_t sa0 = smem_u32(gsm);

    float acc[2][8][4];
#pragma unroll
    for (int mt = 0; mt < 2; mt++)
#pragma unroll
        for (int nt = 0; nt < 8; nt++)
#pragma unroll
            for (int q = 0; q < 4; q++) acc[mt][nt][q] = 0.f;

    const int lrowA = tid >> 1;                 // 0..127
    const int lcA0 = (tid & 1) * 2;             // chunks {0,1} or {2,3}

    auto load_stage = [&](int s, int buf) {
        int p = s >> 5, kb = s & 31;            // p: 0=Whi, 1=Wlo
        int boff = p ? 1024 : 0;
        uint32_t ab = sa0 + buf * GSTAGE_BYTES;
        uint32_t bb = ab + 8192;
        const __half* Ar = A + (size_t)(m0 + lrowA) * CC + kb * 32;
        const __half* Br = W + (size_t)(n0 + lrowA) * KD2 + boff + kb * 32;
#pragma unroll
        for (int c = 0; c < 2; c++) {
            cp_async16(ab + swz(lrowA, lcA0 + c), Ar + (lcA0 + c) * 8);
            cp_async16(bb + swz(lrowA, lcA0 + c), Br + (lcA0 + c) * 8);
        }
    };

    const int NST = 64;                          // 2 passes x 32 k-blocks
    load_stage(0, 0); CP_COMMIT();
    load_stage(1, 1); CP_COMMIT();
    load_stage(2, 2); CP_COMMIT();

    for (int s = 0; s < NST; s++) {
        CP_WAIT2();
        __syncthreads();

        if (s + 3 < NST) load_stage(s + 3, (s + 3) & 3);
        CP_COMMIT();

        uint32_t ab = sa0 + (s & 3) * GSTAGE_BYTES;
        uint32_t bb = ab + 8192;
#pragma unroll
        for (int kk = 0; kk < 2; kk++) {
            uint32_t a[2][4];
#pragma unroll
            for (int mt = 0; mt < 2; mt++) {
                int row = wm * 32 + mt * 16 + (lane & 15);
                int ch = kk * 2 + (lane >> 4);
                ldm_x4(a[mt][0], a[mt][1], a[mt][2], a[mt][3], ab + swz(row, ch));
            }
            uint32_t b[8][2];
#pragma unroll
            for (int nq = 0; nq < 4; nq++) {
                int row = wn * 64 + nq * 16 + ((lane >> 4) & 1) * 8 + (lane & 7);
                int ch = kk * 2 + ((lane >> 3) & 1);
                ldm_x4(b[nq * 2][0], b[nq * 2][1], b[nq * 2 + 1][0], b[nq * 2 + 1][1],
                       bb + swz(row, ch));
            }
#pragma unroll
            for (int mt = 0; mt < 2; mt++)
#pragma unroll
                for (int nt = 0; nt < 8; nt++)
                    mma_fp16(acc[mt][nt][0], acc[mt][nt][1], acc[mt][nt][2], acc[mt][nt][3],
                             a[mt][0], a[mt][1], a[mt][2], a[mt][3],
                             b[nt][0], b[nt][1]);
        }
    }

#pragma unroll
    for (int mt = 0; mt < 2; mt++) {
        int gr = m0 + wm * 32 + mt * 16 + (lane >> 2);
#pragma unroll
        for (int nt = 0; nt < 8; nt++) {
            int gc = n0 + wn * 64 + nt * 8 + (lane & 3) * 2;
            float v0 = acc[mt][nt][0], v1 = acc[mt][nt][1];
            float v2 = acc[mt][nt][2], v3 = acc[mt][nt][3];
            if (epi == 1) {
                v0 = v0 / (1.f + expf(-v0));
                v1 = v1 / (1.f + expf(-v1));
                v2 = v2 / (1.f + expf(-v2));
                v3 = v3 / (1.f + expf(-v3));
            }
            if (epi == 0) {
                float* C = (float*)Cout;
                *(float2*)&C[(size_t)gr * CC + gc]       = make_float2(v0, v1);
                *(float2*)&C[(size_t)(gr + 8) * CC + gc] = make_float2(v2, v3);
            } else {
                __half* C = (__half*)Cout;
                *(uint32_t*)&C[(size_t)gr * CC + gc]       = pack2h(v0, v1);
                *(uint32_t*)&C[(size_t)(gr + 8) * CC + gc] = pack2h(v2, v3);
            }
        }
    }
}

// ---------------------------------------------------------------------------
// 3a) WKV phase 1 (fp16 single-pass): G = (k .* wk)^T v   per (b,h,chunk)
//     A = kT [64][128] (wk folded), B = vT [64][128]; K=128.
// ---------------------------------------------------------------------------
#define P1_KT   0
#define P1_VT   16384
#define P1_PW   32768
#define P1_SMEM (32768 + 640)

__global__ __launch_bounds__(256) void wkv_phase1(
    const __half* __restrict__ Km, const __half* __restrict__ V,
    float* __restrict__ G, const float* __restrict__ tdecay)
{
    extern __shared__ __align__(128) char sm1c[];
    const uint32_t sb = smem_u32(sm1c);
    float* pw = (float*)(sm1c + P1_PW);

    const int tid = threadIdx.x;
    const int wid = tid >> 5, lane = tid & 31;
    const int bhn = blockIdx.x;
    const int n = bhn & 31, bh = bhn >> 5;
    const int b = bh >> 4, h = bh & 15;
    const float decay = __expf(-__expf(tdecay[h]));

    if (tid < 128) pw[tid] = powf(decay, (float)tid);
    __syncthreads();

    const size_t cbase = (size_t)b * TTT * CC + (size_t)h * HS + (size_t)n * TCH * CC;

    // transpose loads: kT[kc][j] = k[j][kc]*pw[127-j], vT[c][j] = v[j][c]
    for (int e = tid; e < 128 * 8; e += 256) {
        int j = e >> 3, c8 = (e & 7) * 8;
        size_t gofs = cbase + (size_t)j * CC + c8;
        HF8 kv, vv;
        kv.u = *(const uint4*)(Km + gofs);
        vv.u = *(const uint4*)(V + gofs);
        float wkj = pw[127 - j];
        uint32_t co = (uint32_t)(j >> 3);
        uint32_t io = (uint32_t)((j & 7) * 2);
#pragma unroll
        for (int q = 0; q < 8; q++) {
            int c = c8 + q;
            *(__half*)(sm1c + P1_KT + swzW(c, co) + io) =
                __float2half_rn(__half2float(kv.h[q]) * wkj);
            *(__half*)(sm1c + P1_VT + swzW(c, co) + io) = vv.h[q];
        }
    }
    __syncthreads();

    // GEMM: warps 4M x 2N, warp tile 16x32, K=128, single fp16 pass
    const int wm = wid & 3;
    const int wn = wid >> 2;
    float acc[4][4];
#pragma unroll
    for (int nt = 0; nt < 4; nt++)
#pragma unroll
        for (int q = 0; q < 4; q++) acc[nt][q] = 0.f;

#pragma unroll
    for (int kk = 0; kk < 8; kk++) {
        uint32_t a[4];
        {
            int row = wm * 16 + (lane & 15);
            int ch = kk * 2 + (lane >> 4);
            ldm_x4(a[0], a[1], a[2], a[3], sb + P1_KT + swzW(row, ch));
        }
        uint32_t bfr[4][2];
#pragma unroll
        for (int nq = 0; nq < 2; nq++) {
            int row = wn * 32 + nq * 16 + ((lane >> 4) & 1) * 8 + (lane & 7);
            int ch = kk * 2 + ((lane >> 3) & 1);
            ldm_x4(bfr[nq * 2][0], bfr[nq * 2][1],
                   bfr[nq * 2 + 1][0], bfr[nq * 2 + 1][1], sb + P1_VT + swzW(row, ch));
        }
#pragma unroll
        for (int nt = 0; nt < 4; nt++)
            mma_fp16(acc[nt][0], acc[nt][1], acc[nt][2], acc[nt][3],
                     a[0], a[1], a[2], a[3], bfr[nt][0], bfr[nt][1]);
    }

    float* Gd = G + (size_t)bhn * (HS * HS);
    int i = wm * 16 + (lane >> 2);
#pragma unroll
    for (int nt = 0; nt < 4; nt++) {
        int c = wn * 32 + nt * 8 + (lane & 3) * 2;
        *(float2*)&Gd[i * 64 + c]       = make_float2(acc[nt][0], acc[nt][1]);
        *(float2*)&Gd[(i + 8) * 64 + c] = make_float2(acc[nt][2], acc[nt][3]);
    }
}

// ---------------------------------------------------------------------------
// 3b) WKV phase 2: in-place scan  buf[n] <- S_n ; S_{n+1} = ws*S_n + G_n
// ---------------------------------------------------------------------------
__global__ __launch_bounds__(256) void wkv_scan(
    float* __restrict__ G, const float* __restrict__ tdecay)
{
    const int tid = threadIdx.x;
    const int bh = blockIdx.x;
    const int h = bh & 15;
    const float decay = __expf(-__expf(tdecay[h]));
    const float ws = powf(decay, 128.f);

    float s[16];
#pragma unroll
    for (int t = 0; t < 16; t++) s[t] = 0.f;

    float* base = G + (size_t)bh * NCH * (HS * HS);
    for (int n = 0; n < NCH; n++) {
        float* p = base + (size_t)n * (HS * HS);
#pragma unroll
        for (int t = 0; t < 16; t++) {
            int idx = tid + t * 256;
            float g = p[idx];
            p[idx] = s[t];
            s[t] = ws * s[t] + g;
        }
    }
}

// ---------------------------------------------------------------------------
// 3c) WKV phase 3 (fp16 single-pass) + fused GroupNorm + gate -> ygb fp16
//     out = (r k^T .* w) v + (r S) .* wb ; y = GN(out/8)*lnw+lnb ; yg = y*g
// ---------------------------------------------------------------------------
#define PH3_R    0                       // 128x64 fp16 (swzA)     16 KB
#define PH3_K    16384                   // 128x64 fp16 (swzA)     16 KB
#define PH3_V    32768                   // vT 64x128 fp16 (swzW)  16 KB
#define PH3_S    49152                   // sT 64x64 fp16 (swzA)    8 KB
#define PH3_ATT  57344                   // 128x128 fp16 (swzW)    32 KB
#define PH3_PW   90112                   //                        0.64 KB
#define PH3_OUT  16384                   // overlays K,V,S: 128x66 fp32 = 33.8 KB
#define PH3_SMEM (90112 + 640)

__global__ __launch_bounds__(256, 2) void wkv_phase3(
    const __half* __restrict__ R, const __half* __restrict__ Km,
    const __half* __restrict__ V, const float* __restrict__ S,
    const __half* __restrict__ GG,
    const float* __restrict__ lnw, const float* __restrict__ lnb,
    __half* __restrict__ YG,
    const float* __restrict__ tdecay, const float* __restrict__ tfaaaa)
{
    extern __shared__ __align__(128) char smc[];
    const uint32_t sb = smem_u32(smc);
    float* pw = (float*)(smc + PH3_PW);

    const int tid = threadIdx.x;
    const int wid = tid >> 5, lane = tid & 31;
    const int bhn = blockIdx.x;
    const int n = bhn & 31, bh = bhn >> 5;
    const int b = bh >> 4, h = bh & 15;
    const float decay = __expf(-__expf(tdecay[h]));
    const float u = tfaaaa[h];

    if (tid < 128) pw[tid] = powf(decay, (float)tid);

    const size_t cbase = (size_t)b * TTT * CC + (size_t)h * HS + (size_t)n * TCH * CC;

    // r, k: direct 16B copies; v: transposed scatter
    for (int e = tid; e < 128 * 8; e += 256) {
        int row = e >> 3, c8 = e & 7;
        size_t gofs = cbase + (size_t)row * CC + c8 * 8;
        uint4 rv = *(const uint4*)(R + gofs);
        uint4 kv = *(const uint4*)(Km + gofs);
        *(uint4*)(smc + PH3_R + swzA(row, c8)) = rv;
        *(uint4*)(smc + PH3_K + swzA(row, c8)) = kv;
        HF8 vv;
        vv.u = *(const uint4*)(V + gofs);
        uint32_t co = (uint32_t)(row >> 3);
        uint32_t io = (uint32_t)((row & 7) * 2);
#pragma unroll
        for (int q = 0; q < 8; q++) {
            int c = c8 * 8 + q;
            *(__half*)(smc + PH3_V + swzW(c, co) + io) = vv.h[q];
        }
    }
    // sT[c][kk] = fp16(S[kk][c])
    {
        const float* Sd = S + (size_t)bhn * (HS * HS);
        for (int e = tid; e < 64 * 16; e += 256) {
            int kkr = e >> 4, c4 = (e & 15) * 4;
            float4 sv = *(const float4*)(Sd + kkr * 64 + c4);
            float sa[4] = {sv.x, sv.y, sv.z, sv.w};
            uint32_t co = (uint32_t)(kkr >> 3);
            uint32_t io = (uint32_t)((kkr & 7) * 2);
#pragma unroll
            for (int q = 0; q < 4; q++) {
                int c = c4 + q;
                *(__half*)(smc + PH3_S + swzA(c, co) + io) = __float2half_rn(sa[q]);
            }
        }
    }
    __syncthreads();

    // ---- ATT GEMM: att = r k^T  (M=128,N=128,K=64), single fp16 pass
    {
        const int wm = wid & 3, wn = wid >> 2;
        float acc[2][8][4];
#pragma unroll
        for (int mt = 0; mt < 2; mt++)
#pragma unroll
            for (int nt = 0; nt < 8; nt++)
#pragma unroll
                for (int q = 0; q < 4; q++) acc[mt][nt][q] = 0.f;

#pragma unroll
        for (int kk = 0; kk < 4; kk++) {
            uint32_t a[2][4];
#pragma unroll
            for (int mt = 0; mt < 2; mt++) {
                int row = wm * 32 + mt * 16 + (lane & 15);
                int ch = kk * 2 + (lane >> 4);
                ldm_x4(a[mt][0], a[mt][1], a[mt][2], a[mt][3], sb + PH3_R + swzA(row, ch));
            }
            uint32_t bfr[8][2];
#pragma unroll
            for (int nq = 0; nq < 4; nq++) {
                int row = wn * 64 + nq * 16 + ((lane >> 4) & 1) * 8 + (lane & 7);
                int ch = kk * 2 + ((lane >> 3) & 1);
                ldm_x4(bfr[nq * 2][0], bfr[nq * 2][1],
                       bfr[nq * 2 + 1][0], bfr[nq * 2 + 1][1], sb + PH3_K + swzA(row, ch));
            }
#pragma unroll
            for (int mt = 0; mt < 2; mt++)
#pragma unroll
                for (int nt = 0; nt < 8; nt++)
                    mma_fp16(acc[mt][nt][0], acc[mt][nt][1], acc[mt][nt][2], acc[mt][nt][3],
                             a[mt][0], a[mt][1], a[mt][2], a[mt][3],
                             bfr[nt][0], bfr[nt][1]);
        }

        // apply w-mask, store att fp16
#pragma unroll
        for (int mt = 0; mt < 2; mt++) {
            int i0 = wm * 32 + mt * 16 + (lane >> 2);
#pragma unroll
            for (int nt = 0; nt < 8; nt++) {
                int j0 = wn * 64 + nt * 8 + (lane & 3) * 2;
#pragma unroll
                for (int rr = 0; rr < 2; rr++) {
                    int i = i0 + rr * 8;
                    float av0 = acc[mt][nt][rr * 2 + 0];
                    float av1 = acc[mt][nt][rr * 2 + 1];
                    int d0 = i - j0, d1 = i - (j0 + 1);
                    float w0 = (d0 > 0) ? pw[d0 - 1] : ((d0 == 0) ? u : 0.f);
                    float w1 = (d1 > 0) ? pw[d1 - 1] : ((d1 == 0) ? u : 0.f);
                    uint32_t off = swzW(i, j0 >> 3) + (j0 & 7) * 2;
                    *(uint32_t*)(smc + PH3_ATT + off) = pack2h(av0 * w0, av1 * w1);
                }
            }
        }
    }
    __syncthreads();

    // ---- OUT GEMMs: acc2 = att @ vT (K=128), acc3 = r @ sT (K=64)
    {
        const int wm = wid & 3, wn = wid >> 2;   // 32 rows, 32 cols
        float acc2[2][4][4], acc3[2][4][4];
#pragma unroll
        for (int mt = 0; mt < 2; mt++)
#pragma unroll
            for (int nt = 0; nt < 4; nt++)
#pragma unroll
                for (int q = 0; q < 4; q++) { acc2[mt][nt][q] = 0.f; acc3[mt][nt][q] = 0.f; }

#pragma unroll
        for (int kk = 0; kk < 8; kk++) {
            uint32_t a[2][4];
#pragma unroll
            for (int mt = 0; mt < 2; mt++) {
                int row = wm * 32 + mt * 16 + (lane & 15);
                int ch = kk * 2 + (lane >> 4);
                ldm_x4(a[mt][0], a[mt][1], a[mt][2], a[mt][3], sb + PH3_ATT + swzW(row, ch));
            }
            uint32_t bfr[4][2];
#pragma unroll
            for (int nq = 0; nq < 2; nq++) {
                int row = wn * 32 + nq * 16 + ((lane >> 4) & 1) * 8 + (lane & 7);
                int ch = kk * 2 + ((lane >> 3) & 1);
                ldm_x4(bfr[nq * 2][0], bfr[nq * 2][1],
                       bfr[nq * 2 + 1][0], bfr[nq * 2 + 1][1], sb + PH3_V + swzW(row, ch));
            }
#pragma unroll
            for (int mt = 0; mt < 2; mt++)
#pragma unroll
                for (int nt = 0; nt < 4; nt++)
                    mma_fp16(acc2[mt][nt][0], acc2[mt][nt][1], acc2[mt][nt][2], acc2[mt][nt][3],
                             a[mt][0], a[mt][1], a[mt][2], a[mt][3],
                             bfr[nt][0], bfr[nt][1]);
        }
#pragma unroll
        for (int kk = 0; kk < 4; kk++) {
            uint32_t a[2][4];
#pragma unroll
            for (int mt = 0; mt < 2; mt++) {
                int row = wm * 32 + mt * 16 + (lane & 15);
                int ch = kk * 2 + (lane >> 4);
                ldm_x4(a[mt][0], a[mt][1], a[mt][2], a[mt][3], sb + PH3_R + swzA(row, ch));
            }
            uint32_t bfr[4][2];
#pragma unroll
            for (int nq = 0; nq < 2; nq++) {
                int row = wn * 32 + nq * 16 + ((lane >> 4) & 1) * 8 + (lane & 7);
                int ch = kk * 2 + ((lane >> 3) & 1);
                ldm_x4(bfr[nq * 2][0], bfr[nq * 2][1],
                       bfr[nq * 2 + 1][0], bfr[nq * 2 + 1][1], sb + PH3_S + swzA(row, ch));
            }
#pragma unroll
            for (int mt = 0; mt < 2; mt++)
#pragma unroll
                for (int nt = 0; nt < 4; nt++)
                    mma_fp16(acc3[mt][nt][0], acc3[mt][nt][1], acc3[mt][nt][2], acc3[mt][nt][3],
                             a[mt][0], a[mt][1], a[mt][2], a[mt][3],
                             bfr[nt][0], bfr[nt][1]);
        }

        __syncthreads();   // all K/V/S reads done before OUT overlay writes

        // out = acc2 + wb[i] * acc3 -> smem (stride 66 floats, overlay K/V/S)
        float* out_s = (float*)(smc + PH3_OUT);
#pragma unroll
        for (int mt = 0; mt < 2; mt++) {
            int i0 = wm * 32 + mt * 16 + (lane >> 2);
#pragma unroll
            for (int nt = 0; nt < 4; nt++) {
                int c = wn * 32 + nt * 8 + (lane & 3) * 2;
                float wb0 = pw[i0], wb1 = pw[i0 + 8];
                *(float2*)&out_s[i0 * 66 + c] =
                    make_float2(acc2[mt][nt][0] + wb0 * acc3[mt][nt][0],
                                acc2[mt][nt][1] + wb0 * acc3[mt][nt][1]);
                *(float2*)&out_s[(i0 + 8) * 66 + c] =
                    make_float2(acc2[mt][nt][2] + wb1 * acc3[mt][nt][2],
                                acc2[mt][nt][3] + wb1 * acc3[mt][nt][3]);
            }
        }
    }
    __syncthreads();

    // ---- fused GroupNorm + gate -> ygb fp16 (warp per row, 16 rows/warp)
    {
        const float* out_s = (const float*)(smc + PH3_OUT);
        float lw0 = lnw[h * HS + lane], lw1 = lnw[h * HS + 32 + lane];
        float lb0 = lnb[h * HS + lane], lb1 = lnb[h * HS + 32 + lane];
        for (int ri = 0; ri < 16; ri++) {
            int i = wid * 16 + ri;
            float a = out_s[i * 66 + lane] * 0.125f;
            float bq = out_s[i * 66 + 32 + lane] * 0.125f;
            float s = a + bq, ss = a * a + bq * bq;
#pragma unroll
            for (int o = 16; o > 0; o >>= 1) {
                s  += __shfl_xor_sync(0xffffffffu, s,  o);
                ss += __shfl_xor_sync(0xffffffffu, ss, o);
            }
            float mean = s * (1.f / 64.f);
            float var  = ss * (1.f / 64.f) - mean * mean;
            float inv  = rsqrtf(var + 1e-5f);

            size_t gofs = cbase + (size_t)i * CC;
            float g0 = __half2float(GG[gofs + lane]);
            float g1 = __half2float(GG[gofs + 32 + lane]);
            float y0 = ((a - mean) * inv * lw0 + lb0) * g0;
            float y1 = ((bq - mean) * inv * lw1 + lb1) * g1;
            YG[gofs + lane]      = __float2half_rn(y0);
            YG[gofs + 32 + lane] = __float2half_rn(y1);
        }
    }
}

// ---------------------------------------------------------------------------
// Launch
// ---------------------------------------------------------------------------
extern "C" void kernel_launch(void* const* d_in, const int* in_sizes, int n_in,
                              void* d_out, int out_size)
{
    const float* x      = (const float*)d_in[0];
    const float* tmk    = (const float*)d_in[1];
    const float* tmv    = (const float*)d_in[2];
    const float* tmr    = (const float*)d_in[3];
    const float* tmg    = (const float*)d_in[4];
    const float* tdecay = (const float*)d_in[5];
    const float* tfaaaa = (const float*)d_in[6];
    const float* Wr     = (const float*)d_in[7];
    const float* Wk     = (const float*)d_in[8];
    const float* Wv     = (const float*)d_in[9];
    const float* Wg     = (const float*)d_in[10];
    const float* Wo     = (const float*)d_in[11];
    const float* lnw    = (const float*)d_in[12];
    const float* lnb    = (const float*)d_in[13];
    float* out = (float*)d_out;

    __half *xr, *xk, *xv, *xg, *ygb, *wr, *wk, *wv, *wg, *wo;
    __half *r, *k, *v, *g;
    float *st;
    cudaGetSymbolAddress((void**)&xr,  g_xr);
    cudaGetSymbolAddress((void**)&xk,  g_xk);
    cudaGetSymbolAddress((void**)&xv,  g_xv);
    cudaGetSymbolAddress((void**)&xg,  g_xg);
    cudaGetSymbolAddress((void**)&ygb, g_ygb);
    cudaGetSymbolAddress((void**)&wr,  g_Wr);
    cudaGetSymbolAddress((void**)&wk,  g_Wk);
    cudaGetSymbolAddress((void**)&wv,  g_Wv);
    cudaGetSymbolAddress((void**)&wg,  g_Wg);
    cudaGetSymbolAddress((void**)&wo,  g_Wo);
    cudaGetSymbolAddress((void**)&r,   g_r);
    cudaGetSymbolAddress((void**)&k,   g_k);
    cudaGetSymbolAddress((void**)&v,   g_v);
    cudaGetSymbolAddress((void**)&g,   g_g);
    cudaGetSymbolAddress((void**)&st,  g_state);

    cudaFuncSetAttribute(gemm_mma,
                         cudaFuncAttributeMaxDynamicSharedMemorySize, GEMM_SMEM);
    cudaFuncSetAttribute(wkv_phase1,
                         cudaFuncAttributeMaxDynamicSharedMemorySize, P1_SMEM);
    cudaFuncSetAttribute(wkv_phase3,
                         cudaFuncAttributeMaxDynamicSharedMemorySize, PH3_SMEM);

    // 0) weight hi/lo fp16 conversion (single launch, 5 weights)
    {
        dim3 cgrid((CC * CC + 255) / 256, 5);
        convw_kernel<<<cgrid, 256>>>(Wr, Wk, Wv, Wg, Wo, wr, wk, wv, wg, wo);
    }

    // 1) mix -> fp16
    {
        int total4 = MM * CC / 4;
        mix_kernel<<<(total4 + 255) / 256, 256>>>(x, tmk, tmv, tmr, tmg,
                                                  xr, xk, xv, xg);
    }

    // 2) projections (fp16 2-pass mma.sync), fp16 outputs
    dim3 ggrid(CC / 128, MM / 128);   // (8, 128)
    gemm_mma<<<ggrid, 256, GEMM_SMEM>>>(xr, wr, r, 2);
    gemm_mma<<<ggrid, 256, GEMM_SMEM>>>(xk, wk, k, 2);
    gemm_mma<<<ggrid, 256, GEMM_SMEM>>>(xv, wv, v, 2);
    gemm_mma<<<ggrid, 256, GEMM_SMEM>>>(xg, wg, g, 1);   // silu + fp16

    // 3) WKV (fp16 single-pass) + fused GroupNorm/gate
    wkv_phase1<<<BB * HH * NCH, 256, P1_SMEM>>>(k, v, st, tdecay);
    wkv_scan<<<BB * HH, 256>>>(st, tdecay);
    wkv_phase3<<<BB * HH * NCH, 256, PH3_SMEM>>>(r, k, v, st, g, lnw, lnb,
                                                 ygb, tdecay, tfaaaa);

    // 4) output projection (writes d_out, fp32)
    gemm_mma<<<ggrid, 256, GEMM_SMEM>>>(ygb, wo, out, 0);
}